// round 10
// baseline (speedup 1.0000x reference)
#include <cuda_runtime.h>
#include <cuda_bf16.h>
#include <cstdint>
#include <math.h>

// Problem constants
#define T_LEN 2048
#define D_DIM 4096
#define NHEAD 32
#define NGRP 8
#define HDIM 128
#define KVDIM 2048   // 2 * HDIM * NGRP

// Scratch (no cudaMalloc allowed)
__device__ float g_q[T_LEN * D_DIM];     // 32 MB
__device__ float g_kv[T_LEN * KVDIM];    // 16 MB
__device__ float g_ctx[T_LEN * D_DIM];   // 32 MB

// ---------------------------------------------------------------------------
// Helpers
// ---------------------------------------------------------------------------
__device__ __forceinline__ uint32_t smem_u32(const void* p) {
    uint32_t a;
    asm("{ .reg .u64 t; cvta.to.shared.u64 t, %1; cvt.u32.u64 %0, t; }"
        : "=r"(a) : "l"(p));
    return a;
}
#define CP_ASYNC16(smem, gptr) \
    asm volatile("cp.async.cg.shared.global [%0], [%1], 16;" \
                 :: "r"(smem), "l"(gptr) : "memory")
#define CP_COMMIT() asm volatile("cp.async.commit_group;" ::: "memory")
#define CP_WAIT(N)  asm volatile("cp.async.wait_group %0;" :: "n"(N) : "memory")

__device__ __forceinline__ uint32_t f2tf32(float f) {
    uint32_t u;
    asm("cvt.rna.tf32.f32 %0, %1;" : "=r"(u) : "f"(f));
    return u;
}
__device__ __forceinline__ void mma_tf32(float* c, const uint32_t* a,
                                         const uint32_t* b) {
    asm volatile(
        "mma.sync.aligned.m16n8k8.row.col.f32.tf32.tf32.f32 "
        "{%0,%1,%2,%3}, {%4,%5,%6,%7}, {%8,%9}, {%0,%1,%2,%3};"
        : "+f"(c[0]), "+f"(c[1]), "+f"(c[2]), "+f"(c[3])
        : "r"(a[0]), "r"(a[1]), "r"(a[2]), "r"(a[3]), "r"(b[0]), "r"(b[1]));
}

// ---------------------------------------------------------------------------
// tf32 mma.sync GEMM, high-occupancy variant.
// C[M,N] = A[M,K] @ B[K,N] (+bias), dual-output fusion via NX0 split.
// BM=128, BN=64, BK=16, 256 threads (8 warps, 4M x 2N), warp tile 32x32.
// acc = 32 regs/thread -> __launch_bounds__(256,4): 4 CTAs/SM, 32 warps.
// 3-stage cp.async ring, ONE barrier per tile.
// Stage smem: A 128x20 + B 16x72 = 3712 f = 14848 B; 3 stages = 44544 B.
// ---------------------------------------------------------------------------
#define GK 4096
#define NT (GK / 16)
#define AS_STRIDE 20
#define BS_STRIDE 72
#define AS_FLOATS (128 * AS_STRIDE)      // 2560
#define BS_FLOATS (16 * BS_STRIDE)       // 1152
#define STAGE_F (AS_FLOATS + BS_FLOATS)  // 3712 floats
#define NSTAGE 3
#define GSMEM_BYTES (NSTAGE * STAGE_F * 4)  // 44544

__global__ __launch_bounds__(256, 4) void gemm_mma(
    const float* __restrict__ A,
    const float* __restrict__ B0, float* __restrict__ C0,
    const float* __restrict__ bias0, int N0, int NX0,
    const float* __restrict__ B1, float* __restrict__ C1, int N1)
{
    extern __shared__ float sh[];
    const uint32_t smb = smem_u32(sh);

    const int tid = threadIdx.x;
    const int wid = tid >> 5;
    const int lane = tid & 31;
    const int gid = lane >> 2;
    const int tig = lane & 3;
    const int warp_m = (wid >> 1) * 32;   // 0,32,64,96
    const int warp_n = (wid & 1) * 32;    // 0,32

    const int by = blockIdx.y;
    int bx = blockIdx.x;

    const float* B; float* C; const float* bias; int N;
    if (bx < NX0) { B = B0; C = C0; bias = bias0; N = N0; }
    else          { B = B1; C = C1; bias = nullptr; N = N1; bx -= NX0; }

    const float* Ab = A + (size_t)by * 128 * GK;
    const float* Bb = B + (size_t)bx * 64;

    // Loader: A 512 chunks (2/thread), B 256 chunks (1/thread)
    const int a_r0 = tid >> 2,         a_c0 = (tid & 3) * 4;
    const int a_r1 = (tid + 256) >> 2, a_c1 = ((tid + 256) & 3) * 4;
    const int b_r  = tid >> 4;            // 0..15
    const int b_c  = (tid & 15) * 4;      // 0..60

    auto load_tile = [&](int kt, int s) {
        const float* ag = Ab + kt * 16;
        const float* bg = Bb + (size_t)(kt * 16) * N;
        uint32_t ab = smb + 4 * (s * STAGE_F);
        uint32_t bb = ab + 4 * AS_FLOATS;
        CP_ASYNC16(ab + (a_r0 * AS_STRIDE + a_c0) * 4,
                   ag + (size_t)a_r0 * GK + a_c0);
        CP_ASYNC16(ab + (a_r1 * AS_STRIDE + a_c1) * 4,
                   ag + (size_t)a_r1 * GK + a_c1);
        CP_ASYNC16(bb + (b_r * BS_STRIDE + b_c) * 4,
                   bg + (size_t)b_r * N + b_c);
        CP_COMMIT();
    };

    float acc[2][4][4];
#pragma unroll
    for (int i = 0; i < 2; i++)
#pragma unroll
        for (int j = 0; j < 4; j++)
#pragma unroll
            for (int k = 0; k < 4; k++) acc[i][j][k] = 0.f;

    load_tile(0, 0);
    load_tile(1, 1);

    for (int kt = 0; kt < NT; kt++) {
        if (kt < NT - 1) { CP_WAIT(1); } else { CP_WAIT(0); }
        __syncthreads();
        if (kt + 2 < NT) load_tile(kt + 2, (kt + 2) % NSTAGE);

        const float* as = sh + (kt % NSTAGE) * STAGE_F;
        const float* bs = as + AS_FLOATS;

#pragma unroll
        for (int ks = 0; ks < 2; ks++) {
            const int k0 = ks * 8;
            uint32_t afr[2][4];
#pragma unroll
            for (int mf = 0; mf < 2; mf++) {
                const float* ap = as + (warp_m + mf * 16 + gid) * AS_STRIDE + k0 + tig;
                afr[mf][0] = f2tf32(ap[0]);
                afr[mf][1] = f2tf32(ap[8 * AS_STRIDE]);
                afr[mf][2] = f2tf32(ap[4]);
                afr[mf][3] = f2tf32(ap[8 * AS_STRIDE + 4]);
            }
            uint32_t bfr[4][2];
#pragma unroll
            for (int nf = 0; nf < 4; nf++) {
                const float* bp = bs + (k0 + tig) * BS_STRIDE + warp_n + nf * 8 + gid;
                bfr[nf][0] = f2tf32(bp[0]);
                bfr[nf][1] = f2tf32(bp[4 * BS_STRIDE]);
            }
#pragma unroll
            for (int mf = 0; mf < 2; mf++)
#pragma unroll
                for (int nf = 0; nf < 4; nf++)
                    mma_tf32(acc[mf][nf], afr[mf], bfr[nf]);
        }
    }

    // Epilogue
#pragma unroll
    for (int mf = 0; mf < 2; mf++) {
#pragma unroll
        for (int nf = 0; nf < 4; nf++) {
            int row0 = by * 128 + warp_m + mf * 16 + gid;
            int col  = bx * 64 + warp_n + nf * 8 + tig * 2;
            float b0 = 0.f, b1 = 0.f;
            if (bias) { b0 = __ldg(bias + col); b1 = __ldg(bias + col + 1); }
            float2 v0 = make_float2(acc[mf][nf][0] + b0, acc[mf][nf][1] + b1);
            float2 v1 = make_float2(acc[mf][nf][2] + b0, acc[mf][nf][3] + b1);
            *(float2*)(C + (size_t)row0 * N + col) = v0;
            *(float2*)(C + (size_t)(row0 + 8) * N + col) = v1;
        }
    }
}

// ---------------------------------------------------------------------------
// Tensor-core causal GQA flash attention (tf32 mma.sync), round-4 proven.
// ---------------------------------------------------------------------------
#define AKPAD 132
#define AVPAD 136
#define APPAD 68
#define ATT_SMEM_UINTS (64 * AKPAD + 64 * AVPAD + 4 * 16 * APPAD)
#define ATT_SMEM_BYTES (ATT_SMEM_UINTS * 4)

__global__ __launch_bounds__(128, 2) void attn_mma(
    const float* __restrict__ q, const float* __restrict__ kv,
    float* __restrict__ ctx)
{
    const int h  = blockIdx.x;
    const int qt = blockIdx.y;
    const int g  = h >> 2;

    extern __shared__ uint32_t smu[];
    uint32_t* Ksh = smu;
    uint32_t* Vsh = Ksh + 64 * AKPAD;
    uint32_t* Psh = Vsh + 64 * AVPAD;

    const int tid  = threadIdx.x;
    const int wid  = tid >> 5;
    const int lane = tid & 31;
    const int gid  = lane >> 2;
    const int tig  = lane & 3;

    uint32_t* Pw = Psh + wid * 16 * APPAD;

    const int r0 = qt * 64 + wid * 16;
    const int rowg0 = r0 + gid;
    const int rowg1 = r0 + gid + 8;

    uint32_t qf[16][4];
    {
        const float* qb = q + (size_t)rowg0 * D_DIM + h * HDIM;
#pragma unroll
        for (int kf = 0; kf < 16; kf++) {
            int c = kf * 8 + tig;
            qf[kf][0] = f2tf32(qb[c]);
            qf[kf][1] = f2tf32(qb[8 * D_DIM + c]);
            qf[kf][2] = f2tf32(qb[c + 4]);
            qf[kf][3] = f2tf32(qb[8 * D_DIM + c + 4]);
        }
    }

    float o[16][4];
#pragma unroll
    for (int nf = 0; nf < 16; nf++)
#pragma unroll
        for (int j = 0; j < 4; j++) o[nf][j] = 0.f;
    float m0 = -1e30f, m1 = -1e30f, l0 = 0.f, l1 = 0.f;
    const float scale = 0.08838834764831845f;

    for (int kt = 0; kt <= qt; kt++) {
        __syncthreads();
        const float* kvb = kv + (size_t)(kt * 64) * KVDIM + g * (2 * HDIM);
        for (int i = tid; i < 64 * 32; i += 128) {
            int row = i >> 5;
            int c4  = (i & 31) * 4;
            float4 kk = *(const float4*)(kvb + (size_t)row * KVDIM + c4);
            float4 vv = *(const float4*)(kvb + (size_t)row * KVDIM + HDIM + c4);
            uint32_t* kp = Ksh + row * AKPAD + c4;
            kp[0] = f2tf32(kk.x); kp[1] = f2tf32(kk.y);
            kp[2] = f2tf32(kk.z); kp[3] = f2tf32(kk.w);
            uint32_t* vp = Vsh + row * AVPAD + c4;
            vp[0] = f2tf32(vv.x); vp[1] = f2tf32(vv.y);
            vp[2] = f2tf32(vv.z); vp[3] = f2tf32(vv.w);
        }
        __syncthreads();

        float sa[8][4];
#pragma unroll
        for (int nf = 0; nf < 8; nf++)
#pragma unroll
            for (int j = 0; j < 4; j++) sa[nf][j] = 0.f;

#pragma unroll
        for (int kf = 0; kf < 16; kf++) {
#pragma unroll
            for (int nf = 0; nf < 8; nf++) {
                const uint32_t* kp = Ksh + (nf * 8 + gid) * AKPAD + kf * 8 + tig;
                uint32_t bfr[2] = { kp[0], kp[4] };
                mma_tf32(sa[nf], qf[kf], bfr);
            }
        }

        const bool diag = (kt == qt);
#pragma unroll
        for (int nf = 0; nf < 8; nf++) {
            int c = kt * 64 + nf * 8 + 2 * tig;
#pragma unroll
            for (int j = 0; j < 4; j++) sa[nf][j] *= scale;
            if (diag) {
                if (c     > rowg0) sa[nf][0] = -1e30f;
                if (c + 1 > rowg0) sa[nf][1] = -1e30f;
                if (c     > rowg1) sa[nf][2] = -1e30f;
                if (c + 1 > rowg1) sa[nf][3] = -1e30f;
            }
        }

        float mx0 = -1e30f, mx1 = -1e30f;
#pragma unroll
        for (int nf = 0; nf < 8; nf++) {
            mx0 = fmaxf(mx0, fmaxf(sa[nf][0], sa[nf][1]));
            mx1 = fmaxf(mx1, fmaxf(sa[nf][2], sa[nf][3]));
        }
        mx0 = fmaxf(mx0, __shfl_xor_sync(0xffffffff, mx0, 1));
        mx0 = fmaxf(mx0, __shfl_xor_sync(0xffffffff, mx0, 2));
        mx1 = fmaxf(mx1, __shfl_xor_sync(0xffffffff, mx1, 1));
        mx1 = fmaxf(mx1, __shfl_xor_sync(0xffffffff, mx1, 2));

        float mn0 = fmaxf(m0, mx0), mn1 = fmaxf(m1, mx1);
        float al0 = __expf(m0 - mn0), al1 = __expf(m1 - mn1);

        float s0 = 0.f, s1 = 0.f;
#pragma unroll
        for (int nf = 0; nf < 8; nf++) {
            float p00 = __expf(sa[nf][0] - mn0);
            float p01 = __expf(sa[nf][1] - mn0);
            float p10 = __expf(sa[nf][2] - mn1);
            float p11 = __expf(sa[nf][3] - mn1);
            s0 += p00 + p01;
            s1 += p10 + p11;
            uint32_t* pp0 = Pw + gid * APPAD + nf * 8 + 2 * tig;
            pp0[0] = f2tf32(p00); pp0[1] = f2tf32(p01);
            uint32_t* pp1 = Pw + (gid + 8) * APPAD + nf * 8 + 2 * tig;
            pp1[0] = f2tf32(p10); pp1[1] = f2tf32(p11);
        }
        s0 += __shfl_xor_sync(0xffffffff, s0, 1);
        s0 += __shfl_xor_sync(0xffffffff, s0, 2);
        s1 += __shfl_xor_sync(0xffffffff, s1, 1);
        s1 += __shfl_xor_sync(0xffffffff, s1, 2);

        l0 = l0 * al0 + s0;
        l1 = l1 * al1 + s1;
        m0 = mn0; m1 = mn1;

#pragma unroll
        for (int nf = 0; nf < 16; nf++) {
            o[nf][0] *= al0; o[nf][1] *= al0;
            o[nf][2] *= al1; o[nf][3] *= al1;
        }
        __syncwarp();

#pragma unroll
        for (int kf = 0; kf < 8; kf++) {
            uint32_t pa[4];
            pa[0] = Pw[gid * APPAD + kf * 8 + tig];
            pa[1] = Pw[(gid + 8) * APPAD + kf * 8 + tig];
            pa[2] = Pw[gid * APPAD + kf * 8 + tig + 4];
            pa[3] = Pw[(gid + 8) * APPAD + kf * 8 + tig + 4];
#pragma unroll
            for (int nf = 0; nf < 16; nf++) {
                const uint32_t* vp = Vsh + (kf * 8 + tig) * AVPAD + nf * 8 + gid;
                uint32_t bfr[2] = { vp[0], vp[4 * AVPAD] };
                mma_tf32(o[nf], pa, bfr);
            }
        }
        __syncwarp();
    }

    float inv0 = 1.0f / l0, inv1 = 1.0f / l1;
    float* cb = ctx + (size_t)rowg0 * D_DIM + h * HDIM;
#pragma unroll
    for (int nf = 0; nf < 16; nf++) {
        int c = nf * 8 + 2 * tig;
        *(float2*)(cb + c) = make_float2(o[nf][0] * inv0, o[nf][1] * inv0);
        *(float2*)(cb + 8 * D_DIM + c) = make_float2(o[nf][2] * inv1, o[nf][3] * inv1);
    }
}

// ---------------------------------------------------------------------------
// Launch
// ---------------------------------------------------------------------------
extern "C" void kernel_launch(void* const* d_in, const int* in_sizes, int n_in,
                              void* d_out, int out_size)
{
    const float* x   = (const float*)d_in[0];
    const float* Wq  = (const float*)d_in[1];
    const float* Wkv = (const float*)d_in[2];
    const float* Wo  = (const float*)d_in[3];
    const float* bo  = (const float*)d_in[4];
    float* out = (float*)d_out;

    float *qp, *kvp, *ctxp;
    cudaGetSymbolAddress((void**)&qp,   g_q);
    cudaGetSymbolAddress((void**)&kvp,  g_kv);
    cudaGetSymbolAddress((void**)&ctxp, g_ctx);

    cudaFuncSetAttribute(attn_mma,
                         cudaFuncAttributeMaxDynamicSharedMemorySize,
                         ATT_SMEM_BYTES);
    cudaFuncSetAttribute(gemm_mma,
                         cudaFuncAttributeMaxDynamicSharedMemorySize,
                         GSMEM_BYTES);

    // 1+2) fused: q = x@Wq (bx<64), kv = x@Wkv (bx>=64)
    gemm_mma<<<dim3(D_DIM / 64 + KVDIM / 64, T_LEN / 128), 256, GSMEM_BYTES>>>(
        x, Wq, qp, nullptr, D_DIM, D_DIM / 64, Wkv, kvp, KVDIM);
    // 3) attention
    attn_mma<<<dim3(NHEAD, T_LEN / 64), 128, ATT_SMEM_BYTES>>>(qp, kvp, ctxp);
    // 4) out = ctx @ Wo + bo
    gemm_mma<<<dim3(D_DIM / 64, T_LEN / 128), 256, GSMEM_BYTES>>>(
        ctxp, Wo, out, bo, D_DIM, D_DIM / 64, Wo, out, D_DIM);

    (void)in_sizes; (void)n_in; (void)out_size;
}

// round 11
// speedup vs baseline: 1.0888x; 1.0888x over previous
#include <cuda_runtime.h>
#include <cuda_bf16.h>
#include <cstdint>
#include <math.h>

// Problem constants
#define T_LEN 2048
#define D_DIM 4096
#define NHEAD 32
#define NGRP 8
#define HDIM 128
#define KVDIM 2048   // 2 * HDIM * NGRP

// Scratch (no cudaMalloc allowed)
__device__ float g_q[T_LEN * D_DIM];     // 32 MB
__device__ float g_kv[T_LEN * KVDIM];    // 16 MB
__device__ float g_ctx[T_LEN * D_DIM];   // 32 MB

// ---------------------------------------------------------------------------
// Helpers
// ---------------------------------------------------------------------------
__device__ __forceinline__ uint32_t smem_u32(const void* p) {
    uint32_t a;
    asm("{ .reg .u64 t; cvta.to.shared.u64 t, %1; cvt.u32.u64 %0, t; }"
        : "=r"(a) : "l"(p));
    return a;
}
#define CP_ASYNC16(smem, gptr) \
    asm volatile("cp.async.cg.shared.global [%0], [%1], 16;" \
                 :: "r"(smem), "l"(gptr) : "memory")
#define CP_COMMIT() asm volatile("cp.async.commit_group;" ::: "memory")
#define CP_WAIT(N)  asm volatile("cp.async.wait_group %0;" :: "n"(N) : "memory")

__device__ __forceinline__ uint32_t f2tf32(float f) {
    uint32_t u;
    asm("cvt.rna.tf32.f32 %0, %1;" : "=r"(u) : "f"(f));
    return u;
}
__device__ __forceinline__ void mma_tf32(float* c, const uint32_t* a,
                                         const uint32_t* b) {
    asm volatile(
        "mma.sync.aligned.m16n8k8.row.col.f32.tf32.tf32.f32 "
        "{%0,%1,%2,%3}, {%4,%5,%6,%7}, {%8,%9}, {%0,%1,%2,%3};"
        : "+f"(c[0]), "+f"(c[1]), "+f"(c[2]), "+f"(c[3])
        : "r"(a[0]), "r"(a[1]), "r"(a[2]), "r"(a[3]), "r"(b[0]), "r"(b[1]));
}

// ---------------------------------------------------------------------------
// tf32 mma.sync GEMM: 128-thread CTAs, 4 warps (2x2), warp tile 64x32.
// C[M,N] = A[M,K] @ B[K,N] (+bias), dual-output fusion via NX0 split.
// BM=128, BN=64, BK=16.  4 CTAs/SM (4 independent barrier domains).
// 3-stage cp.async ring, ONE barrier per tile.
// Stage smem: A 128x20 + B 16x72 = 3712 f = 14848 B; 3 stages = 44544 B.
// ---------------------------------------------------------------------------
#define GK 4096
#define NT (GK / 16)
#define AS_STRIDE 20
#define BS_STRIDE 72
#define AS_FLOATS (128 * AS_STRIDE)      // 2560
#define BS_FLOATS (16 * BS_STRIDE)       // 1152
#define STAGE_F (AS_FLOATS + BS_FLOATS)  // 3712 floats
#define NSTAGE 3
#define GSMEM_BYTES (NSTAGE * STAGE_F * 4)  // 44544

__global__ __launch_bounds__(128, 4) void gemm_mma(
    const float* __restrict__ A,
    const float* __restrict__ B0, float* __restrict__ C0,
    const float* __restrict__ bias0, int N0, int NX0,
    const float* __restrict__ B1, float* __restrict__ C1, int N1)
{
    extern __shared__ float sh[];
    const uint32_t smb = smem_u32(sh);

    const int tid = threadIdx.x;
    const int wid = tid >> 5;
    const int lane = tid & 31;
    const int gid = lane >> 2;
    const int tig = lane & 3;
    const int warp_m = (wid >> 1) * 64;   // 0,64
    const int warp_n = (wid & 1) * 32;    // 0,32

    const int by = blockIdx.y;
    int bx = blockIdx.x;

    const float* B; float* C; const float* bias; int N;
    if (bx < NX0) { B = B0; C = C0; bias = bias0; N = N0; }
    else          { B = B1; C = C1; bias = nullptr; N = N1; bx -= NX0; }

    const float* Ab = A + (size_t)by * 128 * GK;
    const float* Bb = B + (size_t)bx * 64;

    auto load_tile = [&](int kt, int s) {
        const float* ag = Ab + kt * 16;
        const float* bg = Bb + (size_t)(kt * 16) * N;
        uint32_t ab = smb + 4 * (s * STAGE_F);
        uint32_t bb = ab + 4 * AS_FLOATS;
        // A: 512 chunks of 16B (128 rows x 4 per row); 4 per thread
#pragma unroll
        for (int i = 0; i < 4; i++) {
            int id = tid + i * 128;
            int r = id >> 2, c = (id & 3) * 4;
            CP_ASYNC16(ab + (r * AS_STRIDE + c) * 4, ag + (size_t)r * GK + c);
        }
        // B: 256 chunks (16 rows x 16 per row); 2 per thread
#pragma unroll
        for (int i = 0; i < 2; i++) {
            int id = tid + i * 128;
            int r = id >> 4, c = (id & 15) * 4;
            CP_ASYNC16(bb + (r * BS_STRIDE + c) * 4, bg + (size_t)r * N + c);
        }
        CP_COMMIT();
    };

    float acc[4][4][4];
#pragma unroll
    for (int i = 0; i < 4; i++)
#pragma unroll
        for (int j = 0; j < 4; j++)
#pragma unroll
            for (int k = 0; k < 4; k++) acc[i][j][k] = 0.f;

    load_tile(0, 0);
    load_tile(1, 1);

    for (int kt = 0; kt < NT; kt++) {
        if (kt < NT - 1) { CP_WAIT(1); } else { CP_WAIT(0); }
        __syncthreads();
        if (kt + 2 < NT) load_tile(kt + 2, (kt + 2) % NSTAGE);

        const float* as = sh + (kt % NSTAGE) * STAGE_F;
        const float* bs = as + AS_FLOATS;

#pragma unroll
        for (int ks = 0; ks < 2; ks++) {
            const int k0 = ks * 8;
            uint32_t afr[4][4];
#pragma unroll
            for (int mf = 0; mf < 4; mf++) {
                const float* ap = as + (warp_m + mf * 16 + gid) * AS_STRIDE + k0 + tig;
                afr[mf][0] = f2tf32(ap[0]);
                afr[mf][1] = f2tf32(ap[8 * AS_STRIDE]);
                afr[mf][2] = f2tf32(ap[4]);
                afr[mf][3] = f2tf32(ap[8 * AS_STRIDE + 4]);
            }
            uint32_t bfr[4][2];
#pragma unroll
            for (int nf = 0; nf < 4; nf++) {
                const float* bp = bs + (k0 + tig) * BS_STRIDE + warp_n + nf * 8 + gid;
                bfr[nf][0] = f2tf32(bp[0]);
                bfr[nf][1] = f2tf32(bp[4 * BS_STRIDE]);
            }
#pragma unroll
            for (int mf = 0; mf < 4; mf++)
#pragma unroll
                for (int nf = 0; nf < 4; nf++)
                    mma_tf32(acc[mf][nf], afr[mf], bfr[nf]);
        }
    }

    // Epilogue
#pragma unroll
    for (int mf = 0; mf < 4; mf++) {
#pragma unroll
        for (int nf = 0; nf < 4; nf++) {
            int row0 = by * 128 + warp_m + mf * 16 + gid;
            int col  = bx * 64 + warp_n + nf * 8 + tig * 2;
            float b0 = 0.f, b1 = 0.f;
            if (bias) { b0 = __ldg(bias + col); b1 = __ldg(bias + col + 1); }
            float2 v0 = make_float2(acc[mf][nf][0] + b0, acc[mf][nf][1] + b1);
            float2 v1 = make_float2(acc[mf][nf][2] + b0, acc[mf][nf][3] + b1);
            *(float2*)(C + (size_t)row0 * N + col) = v0;
            *(float2*)(C + (size_t)(row0 + 8) * N + col) = v1;
        }
    }
}

// ---------------------------------------------------------------------------
// Tensor-core causal GQA flash attention (tf32 mma.sync), round-4 proven.
// ---------------------------------------------------------------------------
#define AKPAD 132
#define AVPAD 136
#define APPAD 68
#define ATT_SMEM_UINTS (64 * AKPAD + 64 * AVPAD + 4 * 16 * APPAD)
#define ATT_SMEM_BYTES (ATT_SMEM_UINTS * 4)

__global__ __launch_bounds__(128, 2) void attn_mma(
    const float* __restrict__ q, const float* __restrict__ kv,
    float* __restrict__ ctx)
{
    const int h  = blockIdx.x;
    const int qt = blockIdx.y;
    const int g  = h >> 2;

    extern __shared__ uint32_t smu[];
    uint32_t* Ksh = smu;
    uint32_t* Vsh = Ksh + 64 * AKPAD;
    uint32_t* Psh = Vsh + 64 * AVPAD;

    const int tid  = threadIdx.x;
    const int wid  = tid >> 5;
    const int lane = tid & 31;
    const int gid  = lane >> 2;
    const int tig  = lane & 3;

    uint32_t* Pw = Psh + wid * 16 * APPAD;

    const int r0 = qt * 64 + wid * 16;
    const int rowg0 = r0 + gid;
    const int rowg1 = r0 + gid + 8;

    uint32_t qf[16][4];
    {
        const float* qb = q + (size_t)rowg0 * D_DIM + h * HDIM;
#pragma unroll
        for (int kf = 0; kf < 16; kf++) {
            int c = kf * 8 + tig;
            qf[kf][0] = f2tf32(qb[c]);
            qf[kf][1] = f2tf32(qb[8 * D_DIM + c]);
            qf[kf][2] = f2tf32(qb[c + 4]);
            qf[kf][3] = f2tf32(qb[8 * D_DIM + c + 4]);
        }
    }

    float o[16][4];
#pragma unroll
    for (int nf = 0; nf < 16; nf++)
#pragma unroll
        for (int j = 0; j < 4; j++) o[nf][j] = 0.f;
    float m0 = -1e30f, m1 = -1e30f, l0 = 0.f, l1 = 0.f;
    const float scale = 0.08838834764831845f;

    for (int kt = 0; kt <= qt; kt++) {
        __syncthreads();
        const float* kvb = kv + (size_t)(kt * 64) * KVDIM + g * (2 * HDIM);
        for (int i = tid; i < 64 * 32; i += 128) {
            int row = i >> 5;
            int c4  = (i & 31) * 4;
            float4 kk = *(const float4*)(kvb + (size_t)row * KVDIM + c4);
            float4 vv = *(const float4*)(kvb + (size_t)row * KVDIM + HDIM + c4);
            uint32_t* kp = Ksh + row * AKPAD + c4;
            kp[0] = f2tf32(kk.x); kp[1] = f2tf32(kk.y);
            kp[2] = f2tf32(kk.z); kp[3] = f2tf32(kk.w);
            uint32_t* vp = Vsh + row * AVPAD + c4;
            vp[0] = f2tf32(vv.x); vp[1] = f2tf32(vv.y);
            vp[2] = f2tf32(vv.z); vp[3] = f2tf32(vv.w);
        }
        __syncthreads();

        float sa[8][4];
#pragma unroll
        for (int nf = 0; nf < 8; nf++)
#pragma unroll
            for (int j = 0; j < 4; j++) sa[nf][j] = 0.f;

#pragma unroll
        for (int kf = 0; kf < 16; kf++) {
#pragma unroll
            for (int nf = 0; nf < 8; nf++) {
                const uint32_t* kp = Ksh + (nf * 8 + gid) * AKPAD + kf * 8 + tig;
                uint32_t bfr[2] = { kp[0], kp[4] };
                mma_tf32(sa[nf], qf[kf], bfr);
            }
        }

        const bool diag = (kt == qt);
#pragma unroll
        for (int nf = 0; nf < 8; nf++) {
            int c = kt * 64 + nf * 8 + 2 * tig;
#pragma unroll
            for (int j = 0; j < 4; j++) sa[nf][j] *= scale;
            if (diag) {
                if (c     > rowg0) sa[nf][0] = -1e30f;
                if (c + 1 > rowg0) sa[nf][1] = -1e30f;
                if (c     > rowg1) sa[nf][2] = -1e30f;
                if (c + 1 > rowg1) sa[nf][3] = -1e30f;
            }
        }

        float mx0 = -1e30f, mx1 = -1e30f;
#pragma unroll
        for (int nf = 0; nf < 8; nf++) {
            mx0 = fmaxf(mx0, fmaxf(sa[nf][0], sa[nf][1]));
            mx1 = fmaxf(mx1, fmaxf(sa[nf][2], sa[nf][3]));
        }
        mx0 = fmaxf(mx0, __shfl_xor_sync(0xffffffff, mx0, 1));
        mx0 = fmaxf(mx0, __shfl_xor_sync(0xffffffff, mx0, 2));
        mx1 = fmaxf(mx1, __shfl_xor_sync(0xffffffff, mx1, 1));
        mx1 = fmaxf(mx1, __shfl_xor_sync(0xffffffff, mx1, 2));

        float mn0 = fmaxf(m0, mx0), mn1 = fmaxf(m1, mx1);
        float al0 = __expf(m0 - mn0), al1 = __expf(m1 - mn1);

        float s0 = 0.f, s1 = 0.f;
#pragma unroll
        for (int nf = 0; nf < 8; nf++) {
            float p00 = __expf(sa[nf][0] - mn0);
            float p01 = __expf(sa[nf][1] - mn0);
            float p10 = __expf(sa[nf][2] - mn1);
            float p11 = __expf(sa[nf][3] - mn1);
            s0 += p00 + p01;
            s1 += p10 + p11;
            uint32_t* pp0 = Pw + gid * APPAD + nf * 8 + 2 * tig;
            pp0[0] = f2tf32(p00); pp0[1] = f2tf32(p01);
            uint32_t* pp1 = Pw + (gid + 8) * APPAD + nf * 8 + 2 * tig;
            pp1[0] = f2tf32(p10); pp1[1] = f2tf32(p11);
        }
        s0 += __shfl_xor_sync(0xffffffff, s0, 1);
        s0 += __shfl_xor_sync(0xffffffff, s0, 2);
        s1 += __shfl_xor_sync(0xffffffff, s1, 1);
        s1 += __shfl_xor_sync(0xffffffff, s1, 2);

        l0 = l0 * al0 + s0;
        l1 = l1 * al1 + s1;
        m0 = mn0; m1 = mn1;

#pragma unroll
        for (int nf = 0; nf < 16; nf++) {
            o[nf][0] *= al0; o[nf][1] *= al0;
            o[nf][2] *= al1; o[nf][3] *= al1;
        }
        __syncwarp();

#pragma unroll
        for (int kf = 0; kf < 8; kf++) {
            uint32_t pa[4];
            pa[0] = Pw[gid * APPAD + kf * 8 + tig];
            pa[1] = Pw[(gid + 8) * APPAD + kf * 8 + tig];
            pa[2] = Pw[gid * APPAD + kf * 8 + tig + 4];
            pa[3] = Pw[(gid + 8) * APPAD + kf * 8 + tig + 4];
#pragma unroll
            for (int nf = 0; nf < 16; nf++) {
                const uint32_t* vp = Vsh + (kf * 8 + tig) * AVPAD + nf * 8 + gid;
                uint32_t bfr[2] = { vp[0], vp[4 * AVPAD] };
                mma_tf32(o[nf], pa, bfr);
            }
        }
        __syncwarp();
    }

    float inv0 = 1.0f / l0, inv1 = 1.0f / l1;
    float* cb = ctx + (size_t)rowg0 * D_DIM + h * HDIM;
#pragma unroll
    for (int nf = 0; nf < 16; nf++) {
        int c = nf * 8 + 2 * tig;
        *(float2*)(cb + c) = make_float2(o[nf][0] * inv0, o[nf][1] * inv0);
        *(float2*)(cb + 8 * D_DIM + c) = make_float2(o[nf][2] * inv1, o[nf][3] * inv1);
    }
}

// ---------------------------------------------------------------------------
// Launch
// ---------------------------------------------------------------------------
extern "C" void kernel_launch(void* const* d_in, const int* in_sizes, int n_in,
                              void* d_out, int out_size)
{
    const float* x   = (const float*)d_in[0];
    const float* Wq  = (const float*)d_in[1];
    const float* Wkv = (const float*)d_in[2];
    const float* Wo  = (const float*)d_in[3];
    const float* bo  = (const float*)d_in[4];
    float* out = (float*)d_out;

    float *qp, *kvp, *ctxp;
    cudaGetSymbolAddress((void**)&qp,   g_q);
    cudaGetSymbolAddress((void**)&kvp,  g_kv);
    cudaGetSymbolAddress((void**)&ctxp, g_ctx);

    cudaFuncSetAttribute(attn_mma,
                         cudaFuncAttributeMaxDynamicSharedMemorySize,
                         ATT_SMEM_BYTES);
    cudaFuncSetAttribute(gemm_mma,
                         cudaFuncAttributeMaxDynamicSharedMemorySize,
                         GSMEM_BYTES);

    // 1+2) fused: q = x@Wq (bx<64), kv = x@Wkv (bx>=64)
    gemm_mma<<<dim3(D_DIM / 64 + KVDIM / 64, T_LEN / 128), 128, GSMEM_BYTES>>>(
        x, Wq, qp, nullptr, D_DIM, D_DIM / 64, Wkv, kvp, KVDIM);
    // 3) attention
    attn_mma<<<dim3(NHEAD, T_LEN / 64), 128, ATT_SMEM_BYTES>>>(qp, kvp, ctxp);
    // 4) out = ctx @ Wo + bo
    gemm_mma<<<dim3(D_DIM / 64, T_LEN / 128), 128, GSMEM_BYTES>>>(
        ctxp, Wo, out, bo, D_DIM, D_DIM / 64, Wo, out, D_DIM);

    (void)in_sizes; (void)n_in; (void)out_size;
}

// round 12
// speedup vs baseline: 1.6866x; 1.5490x over previous
#include <cuda_runtime.h>
#include <cuda_fp16.h>
#include <cuda_bf16.h>
#include <cstdint>
#include <math.h>

// Problem constants
#define T_LEN 2048
#define D_DIM 4096
#define NHEAD 32
#define NGRP 8
#define HDIM 128
#define KVDIM 2048   // 2 * HDIM * NGRP

// Scratch (no cudaMalloc allowed)
__device__ float    g_q[T_LEN * D_DIM];          // 32 MB f32
__device__ float    g_kv[T_LEN * KVDIM];         // 16 MB f32
__device__ uint32_t g_ctxh[T_LEN * D_DIM / 2];   // 16 MB half2-packed ctx
__device__ uint32_t g_xh[T_LEN * D_DIM / 2];     // 16 MB x  half2 [T][D/2]
__device__ uint32_t g_wqh[D_DIM / 2 * D_DIM];    // 32 MB Wq  kp-major [K/2][N]
__device__ uint32_t g_wkvh[D_DIM / 2 * KVDIM];   // 16 MB Wkv [K/2][N]
__device__ uint32_t g_woh[D_DIM / 2 * D_DIM];    // 32 MB Wo  [K/2][N]

// ---------------------------------------------------------------------------
// Helpers
// ---------------------------------------------------------------------------
__device__ __forceinline__ uint32_t smem_u32(const void* p) {
    uint32_t a;
    asm("{ .reg .u64 t; cvta.to.shared.u64 t, %1; cvt.u32.u64 %0, t; }"
        : "=r"(a) : "l"(p));
    return a;
}
#define CP_ASYNC16(smem, gptr) \
    asm volatile("cp.async.cg.shared.global [%0], [%1], 16;" \
                 :: "r"(smem), "l"(gptr) : "memory")
#define CP_COMMIT() asm volatile("cp.async.commit_group;" ::: "memory")
#define CP_WAIT(N)  asm volatile("cp.async.wait_group %0;" :: "n"(N) : "memory")

__device__ __forceinline__ uint32_t f2tf32(float f) {
    uint32_t u;
    asm("cvt.rna.tf32.f32 %0, %1;" : "=r"(u) : "f"(f));
    return u;
}
__device__ __forceinline__ uint32_t packh2(float a, float b) {
    __half2 h = __floats2half2_rn(a, b);
    return *reinterpret_cast<uint32_t*>(&h);
}
__device__ __forceinline__ void mma_tf32(float* c, const uint32_t* a,
                                         const uint32_t* b) {
    asm volatile(
        "mma.sync.aligned.m16n8k8.row.col.f32.tf32.tf32.f32 "
        "{%0,%1,%2,%3}, {%4,%5,%6,%7}, {%8,%9}, {%0,%1,%2,%3};"
        : "+f"(c[0]), "+f"(c[1]), "+f"(c[2]), "+f"(c[3])
        : "r"(a[0]), "r"(a[1]), "r"(a[2]), "r"(a[3]), "r"(b[0]), "r"(b[1]));
}
__device__ __forceinline__ void mma_f16(float* c, const uint32_t* a,
                                        const uint32_t* b) {
    asm volatile(
        "mma.sync.aligned.m16n8k16.row.col.f32.f16.f16.f32 "
        "{%0,%1,%2,%3}, {%4,%5,%6,%7}, {%8,%9}, {%0,%1,%2,%3};"
        : "+f"(c[0]), "+f"(c[1]), "+f"(c[2]), "+f"(c[3])
        : "r"(a[0]), "r"(a[1]), "r"(a[2]), "r"(a[3]), "r"(b[0]), "r"(b[1]));
}

// ---------------------------------------------------------------------------
// Prepass: pack fp32 rows into k-paired half2.
// pack_flat: out[i] = half2(in[2i], in[2i+1])   (A operands, k contiguous)
// pack_w:    out[kp*N+n] = half2(W[2kp*N+n], W[(2kp+1)*N+n])
// ---------------------------------------------------------------------------
__global__ __launch_bounds__(256) void pack_flat(
    const float2* __restrict__ in, uint32_t* __restrict__ out, int n2)
{
    int i = blockIdx.x * 256 + threadIdx.x;
    if (i < n2) {
        float2 v = in[i];
        out[i] = packh2(v.x, v.y);
    }
}
__global__ __launch_bounds__(256) void pack_w(
    const float* __restrict__ in, uint32_t* __restrict__ out, int N)
{
    int n = blockIdx.x * 256 + threadIdx.x;
    int kp = blockIdx.y;
    float a = in[(size_t)(2 * kp) * N + n];
    float b = in[(size_t)(2 * kp + 1) * N + n];
    out[(size_t)kp * N + n] = packh2(a, b);
}

// ---------------------------------------------------------------------------
// fp16 mma.sync GEMM (m16n8k16): C[M,N] = A[M,K] @ B[K,N] (+bias).
// A: half2-packed [M][K/2] u32.  B: kp-major [K/2][N] u32.
// BM=128, BN=128, BK=32 elements (16 kpairs), 256 threads (8 warps 2x4),
// warp tile 64x32.  3-stage cp.async ring, ONE barrier per tile.
// Fragment addressing identical to the proven tf32 kernel (kp units).
// Stage: A 128x20 u32 + B 16x136 u32 = 18944 B; 3 stages = 56832 B.
// ---------------------------------------------------------------------------
#define GK2 2048               // K/2 u32 per A row
#define NT 128                 // 4096 / 32
#define AS_STRIDE 20
#define BS_STRIDE 136
#define AS_U (128 * AS_STRIDE)     // 2560
#define BS_U (16 * BS_STRIDE)      // 2176
#define STAGE_U (AS_U + BS_U)      // 4736
#define NSTAGE 3
#define GSMEM_BYTES (NSTAGE * STAGE_U * 4)   // 56832

__global__ __launch_bounds__(256, 2) void gemm_h(
    const uint32_t* __restrict__ A,
    const uint32_t* __restrict__ B0, float* __restrict__ C0,
    const float* __restrict__ bias0, int N0, int NX0,
    const uint32_t* __restrict__ B1, float* __restrict__ C1, int N1)
{
    extern __shared__ uint32_t sh[];
    const uint32_t smb = smem_u32(sh);

    const int tid = threadIdx.x;
    const int wid = tid >> 5;
    const int lane = tid & 31;
    const int gid = lane >> 2;
    const int tig = lane & 3;
    const int warp_m = (wid & 1) * 64;
    const int warp_n = (wid >> 1) * 32;

    const int by = blockIdx.y;
    int bx = blockIdx.x;

    const uint32_t* B; float* C; const float* bias; int N;
    if (bx < NX0) { B = B0; C = C0; bias = bias0; N = N0; }
    else          { B = B1; C = C1; bias = nullptr; N = N1; bx -= NX0; }

    const uint32_t* Ab = A + (size_t)by * 128 * GK2;
    const uint32_t* Bb = B + (size_t)bx * 128;

    auto load_tile = [&](int kt, int s) {
        const uint32_t* ag = Ab + kt * 16;
        const uint32_t* bg = Bb + (size_t)(kt * 16) * N;
        uint32_t ab = smb + 4 * (s * STAGE_U);
        uint32_t bb = ab + 4 * AS_U;
        // A: 512 chunks (128 rows x 4), 2 per thread
#pragma unroll
        for (int i = 0; i < 2; i++) {
            int id = tid + i * 256;
            int r = id >> 2, c = (id & 3) * 4;
            CP_ASYNC16(ab + (r * AS_STRIDE + c) * 4, ag + (size_t)r * GK2 + c);
        }
        // B: 512 chunks (16 kp-rows x 32), 2 per thread
#pragma unroll
        for (int i = 0; i < 2; i++) {
            int id = tid + i * 256;
            int r = id >> 5, c = (id & 31) * 4;
            CP_ASYNC16(bb + (r * BS_STRIDE + c) * 4, bg + (size_t)r * N + c);
        }
        CP_COMMIT();
    };

    float acc[4][4][4];
#pragma unroll
    for (int i = 0; i < 4; i++)
#pragma unroll
        for (int j = 0; j < 4; j++)
#pragma unroll
            for (int k = 0; k < 4; k++) acc[i][j][k] = 0.f;

    load_tile(0, 0);
    load_tile(1, 1);

    for (int kt = 0; kt < NT; kt++) {
        if (kt < NT - 1) { CP_WAIT(1); } else { CP_WAIT(0); }
        __syncthreads();
        if (kt + 2 < NT) load_tile(kt + 2, (kt + 2) % NSTAGE);

        const uint32_t* as = sh + (kt % NSTAGE) * STAGE_U;
        const uint32_t* bs = as + AS_U;

#pragma unroll
        for (int ks = 0; ks < 2; ks++) {       // two k16 steps (8 kpairs each)
            const int k0 = ks * 8;
            uint32_t afr[4][4];
#pragma unroll
            for (int mf = 0; mf < 4; mf++) {
                const uint32_t* ap = as + (warp_m + mf * 16 + gid) * AS_STRIDE + k0 + tig;
                afr[mf][0] = ap[0];
                afr[mf][1] = ap[8 * AS_STRIDE];
                afr[mf][2] = ap[4];
                afr[mf][3] = ap[8 * AS_STRIDE + 4];
            }
            uint32_t bfr[4][2];
#pragma unroll
            for (int nf = 0; nf < 4; nf++) {
                const uint32_t* bp = bs + (k0 + tig) * BS_STRIDE + warp_n + nf * 8 + gid;
                bfr[nf][0] = bp[0];
                bfr[nf][1] = bp[4 * BS_STRIDE];
            }
#pragma unroll
            for (int mf = 0; mf < 4; mf++)
#pragma unroll
                for (int nf = 0; nf < 4; nf++)
                    mma_f16(acc[mf][nf], afr[mf], bfr[nf]);
        }
    }

    // Epilogue
#pragma unroll
    for (int mf = 0; mf < 4; mf++) {
#pragma unroll
        for (int nf = 0; nf < 4; nf++) {
            int row0 = by * 128 + warp_m + mf * 16 + gid;
            int col  = bx * 128 + warp_n + nf * 8 + tig * 2;
            float b0 = 0.f, b1 = 0.f;
            if (bias) { b0 = __ldg(bias + col); b1 = __ldg(bias + col + 1); }
            float2 v0 = make_float2(acc[mf][nf][0] + b0, acc[mf][nf][1] + b1);
            float2 v1 = make_float2(acc[mf][nf][2] + b0, acc[mf][nf][3] + b1);
            *(float2*)(C + (size_t)row0 * N + col) = v0;
            *(float2*)(C + (size_t)(row0 + 8) * N + col) = v1;
        }
    }
}

// ---------------------------------------------------------------------------
// Tensor-core causal GQA flash attention (tf32 mma.sync), round-4 proven.
// Epilogue writes ctx as half2-packed u32 (feeds gemm3 directly).
// ---------------------------------------------------------------------------
#define AKPAD 132
#define AVPAD 136
#define APPAD 68
#define ATT_SMEM_UINTS (64 * AKPAD + 64 * AVPAD + 4 * 16 * APPAD)
#define ATT_SMEM_BYTES (ATT_SMEM_UINTS * 4)

__global__ __launch_bounds__(128, 2) void attn_mma(
    const float* __restrict__ q, const float* __restrict__ kv,
    uint32_t* __restrict__ ctxh)
{
    const int h  = blockIdx.x;
    const int qt = blockIdx.y;
    const int g  = h >> 2;

    extern __shared__ uint32_t smu[];
    uint32_t* Ksh = smu;
    uint32_t* Vsh = Ksh + 64 * AKPAD;
    uint32_t* Psh = Vsh + 64 * AVPAD;

    const int tid  = threadIdx.x;
    const int wid  = tid >> 5;
    const int lane = tid & 31;
    const int gid  = lane >> 2;
    const int tig  = lane & 3;

    uint32_t* Pw = Psh + wid * 16 * APPAD;

    const int r0 = qt * 64 + wid * 16;
    const int rowg0 = r0 + gid;
    const int rowg1 = r0 + gid + 8;

    uint32_t qf[16][4];
    {
        const float* qb = q + (size_t)rowg0 * D_DIM + h * HDIM;
#pragma unroll
        for (int kf = 0; kf < 16; kf++) {
            int c = kf * 8 + tig;
            qf[kf][0] = f2tf32(qb[c]);
            qf[kf][1] = f2tf32(qb[8 * D_DIM + c]);
            qf[kf][2] = f2tf32(qb[c + 4]);
            qf[kf][3] = f2tf32(qb[8 * D_DIM + c + 4]);
        }
    }

    float o[16][4];
#pragma unroll
    for (int nf = 0; nf < 16; nf++)
#pragma unroll
        for (int j = 0; j < 4; j++) o[nf][j] = 0.f;
    float m0 = -1e30f, m1 = -1e30f, l0 = 0.f, l1 = 0.f;
    const float scale = 0.08838834764831845f;

    for (int kt = 0; kt <= qt; kt++) {
        __syncthreads();
        const float* kvb = kv + (size_t)(kt * 64) * KVDIM + g * (2 * HDIM);
        for (int i = tid; i < 64 * 32; i += 128) {
            int row = i >> 5;
            int c4  = (i & 31) * 4;
            float4 kk = *(const float4*)(kvb + (size_t)row * KVDIM + c4);
            float4 vv = *(const float4*)(kvb + (size_t)row * KVDIM + HDIM + c4);
            uint32_t* kp = Ksh + row * AKPAD + c4;
            kp[0] = f2tf32(kk.x); kp[1] = f2tf32(kk.y);
            kp[2] = f2tf32(kk.z); kp[3] = f2tf32(kk.w);
            uint32_t* vp = Vsh + row * AVPAD + c4;
            vp[0] = f2tf32(vv.x); vp[1] = f2tf32(vv.y);
            vp[2] = f2tf32(vv.z); vp[3] = f2tf32(vv.w);
        }
        __syncthreads();

        float sa[8][4];
#pragma unroll
        for (int nf = 0; nf < 8; nf++)
#pragma unroll
            for (int j = 0; j < 4; j++) sa[nf][j] = 0.f;

#pragma unroll
        for (int kf = 0; kf < 16; kf++) {
#pragma unroll
            for (int nf = 0; nf < 8; nf++) {
                const uint32_t* kp = Ksh + (nf * 8 + gid) * AKPAD + kf * 8 + tig;
                uint32_t bfr[2] = { kp[0], kp[4] };
                mma_tf32(sa[nf], qf[kf], bfr);
            }
        }

        const bool diag = (kt == qt);
#pragma unroll
        for (int nf = 0; nf < 8; nf++) {
            int c = kt * 64 + nf * 8 + 2 * tig;
#pragma unroll
            for (int j = 0; j < 4; j++) sa[nf][j] *= scale;
            if (diag) {
                if (c     > rowg0) sa[nf][0] = -1e30f;
                if (c + 1 > rowg0) sa[nf][1] = -1e30f;
                if (c     > rowg1) sa[nf][2] = -1e30f;
                if (c + 1 > rowg1) sa[nf][3] = -1e30f;
            }
        }

        float mx0 = -1e30f, mx1 = -1e30f;
#pragma unroll
        for (int nf = 0; nf < 8; nf++) {
            mx0 = fmaxf(mx0, fmaxf(sa[nf][0], sa[nf][1]));
            mx1 = fmaxf(mx1, fmaxf(sa[nf][2], sa[nf][3]));
        }
        mx0 = fmaxf(mx0, __shfl_xor_sync(0xffffffff, mx0, 1));
        mx0 = fmaxf(mx0, __shfl_xor_sync(0xffffffff, mx0, 2));
        mx1 = fmaxf(mx1, __shfl_xor_sync(0xffffffff, mx1, 1));
        mx1 = fmaxf(mx1, __shfl_xor_sync(0xffffffff, mx1, 2));

        float mn0 = fmaxf(m0, mx0), mn1 = fmaxf(m1, mx1);
        float al0 = __expf(m0 - mn0), al1 = __expf(m1 - mn1);

        float s0 = 0.f, s1 = 0.f;
#pragma unroll
        for (int nf = 0; nf < 8; nf++) {
            float p00 = __expf(sa[nf][0] - mn0);
            float p01 = __expf(sa[nf][1] - mn0);
            float p10 = __expf(sa[nf][2] - mn1);
            float p11 = __expf(sa[nf][3] - mn1);
            s0 += p00 + p01;
            s1 += p10 + p11;
            uint32_t* pp0 = Pw + gid * APPAD + nf * 8 + 2 * tig;
            pp0[0] = f2tf32(p00); pp0[1] = f2tf32(p01);
            uint32_t* pp1 = Pw + (gid + 8) * APPAD + nf * 8 + 2 * tig;
            pp1[0] = f2tf32(p10); pp1[1] = f2tf32(p11);
        }
        s0 += __shfl_xor_sync(0xffffffff, s0, 1);
        s0 += __shfl_xor_sync(0xffffffff, s0, 2);
        s1 += __shfl_xor_sync(0xffffffff, s1, 1);
        s1 += __shfl_xor_sync(0xffffffff, s1, 2);

        l0 = l0 * al0 + s0;
        l1 = l1 * al1 + s1;
        m0 = mn0; m1 = mn1;

#pragma unroll
        for (int nf = 0; nf < 16; nf++) {
            o[nf][0] *= al0; o[nf][1] *= al0;
            o[nf][2] *= al1; o[nf][3] *= al1;
        }
        __syncwarp();

#pragma unroll
        for (int kf = 0; kf < 8; kf++) {
            uint32_t pa[4];
            pa[0] = Pw[gid * APPAD + kf * 8 + tig];
            pa[1] = Pw[(gid + 8) * APPAD + kf * 8 + tig];
            pa[2] = Pw[gid * APPAD + kf * 8 + tig + 4];
            pa[3] = Pw[(gid + 8) * APPAD + kf * 8 + tig + 4];
#pragma unroll
            for (int nf = 0; nf < 16; nf++) {
                const uint32_t* vp = Vsh + (kf * 8 + tig) * AVPAD + nf * 8 + gid;
                uint32_t bfr[2] = { vp[0], vp[4 * AVPAD] };
                mma_tf32(o[nf], pa, bfr);
            }
        }
        __syncwarp();
    }

    // Normalize + write half2-packed ctx: pair index = (h*128 + nf*8 + 2tig)/2
    float inv0 = 1.0f / l0, inv1 = 1.0f / l1;
    uint32_t* cb = ctxh + (size_t)rowg0 * (D_DIM / 2) + h * (HDIM / 2);
#pragma unroll
    for (int nf = 0; nf < 16; nf++) {
        int cp = nf * 4 + tig;
        cb[cp] = packh2(o[nf][0] * inv0, o[nf][1] * inv0);
        cb[8 * (D_DIM / 2) + cp] = packh2(o[nf][2] * inv1, o[nf][3] * inv1);
    }
}

// ---------------------------------------------------------------------------
// Launch
// ---------------------------------------------------------------------------
extern "C" void kernel_launch(void* const* d_in, const int* in_sizes, int n_in,
                              void* d_out, int out_size)
{
    const float* x   = (const float*)d_in[0];
    const float* Wq  = (const float*)d_in[1];
    const float* Wkv = (const float*)d_in[2];
    const float* Wo  = (const float*)d_in[3];
    const float* bo  = (const float*)d_in[4];
    float* out = (float*)d_out;

    float *qp, *kvp;
    uint32_t *ctxh, *xh, *wqh, *wkvh, *woh;
    cudaGetSymbolAddress((void**)&qp,   g_q);
    cudaGetSymbolAddress((void**)&kvp,  g_kv);
    cudaGetSymbolAddress((void**)&ctxh, g_ctxh);
    cudaGetSymbolAddress((void**)&xh,   g_xh);
    cudaGetSymbolAddress((void**)&wqh,  g_wqh);
    cudaGetSymbolAddress((void**)&wkvh, g_wkvh);
    cudaGetSymbolAddress((void**)&woh,  g_woh);

    cudaFuncSetAttribute(attn_mma,
                         cudaFuncAttributeMaxDynamicSharedMemorySize,
                         ATT_SMEM_BYTES);
    cudaFuncSetAttribute(gemm_h,
                         cudaFuncAttributeMaxDynamicSharedMemorySize,
                         GSMEM_BYTES);

    // Prepass: pack operands to fp16
    pack_flat<<<T_LEN * D_DIM / 2 / 256, 256>>>(
        (const float2*)x, xh, T_LEN * D_DIM / 2);
    pack_w<<<dim3(D_DIM / 256, D_DIM / 2), 256>>>(Wq, wqh, D_DIM);
    pack_w<<<dim3(KVDIM / 256, D_DIM / 2), 256>>>(Wkv, wkvh, KVDIM);
    pack_w<<<dim3(D_DIM / 256, D_DIM / 2), 256>>>(Wo, woh, D_DIM);

    // 1+2) fused: q = x@Wq (bx<32), kv = x@Wkv (bx>=32)
    gemm_h<<<dim3(D_DIM / 128 + KVDIM / 128, T_LEN / 128), 256, GSMEM_BYTES>>>(
        xh, wqh, qp, nullptr, D_DIM, D_DIM / 128, wkvh, kvp, KVDIM);
    // 3) attention (writes half2-packed ctx)
    attn_mma<<<dim3(NHEAD, T_LEN / 64), 128, ATT_SMEM_BYTES>>>(qp, kvp, ctxh);
    // 4) out = ctx @ Wo + bo
    gemm_h<<<dim3(D_DIM / 128, T_LEN / 128), 256, GSMEM_BYTES>>>(
        ctxh, woh, out, bo, D_DIM, D_DIM / 128, woh, out, D_DIM);

    (void)in_sizes; (void)n_in; (void)out_size;
}

// round 13
// speedup vs baseline: 1.8330x; 1.0868x over previous
#include <cuda_runtime.h>
#include <cuda_fp16.h>
#include <cuda_bf16.h>
#include <cstdint>
#include <math.h>

// Problem constants
#define T_LEN 2048
#define D_DIM 4096
#define NHEAD 32
#define NGRP 8
#define HDIM 128
#define KVDIM 2048   // 2 * HDIM * NGRP

// Scratch (no cudaMalloc allowed)
__device__ float    g_q[T_LEN * D_DIM];          // 32 MB f32
__device__ float    g_kv[T_LEN * KVDIM];         // 16 MB f32
__device__ uint32_t g_ctxh[T_LEN * D_DIM / 2];   // 16 MB half2-packed ctx
__device__ uint32_t g_xh[T_LEN * D_DIM / 2];     // 16 MB x  half2 [T][D/2]
__device__ uint32_t g_wqh[D_DIM / 2 * D_DIM];    // 32 MB Wq  kp-major [K/2][N]
__device__ uint32_t g_wkvh[D_DIM / 2 * KVDIM];   // 16 MB Wkv [K/2][N]
__device__ uint32_t g_woh[D_DIM / 2 * D_DIM];    // 32 MB Wo  [K/2][N]

// ---------------------------------------------------------------------------
// Helpers
// ---------------------------------------------------------------------------
__device__ __forceinline__ uint32_t smem_u32(const void* p) {
    uint32_t a;
    asm("{ .reg .u64 t; cvta.to.shared.u64 t, %1; cvt.u32.u64 %0, t; }"
        : "=r"(a) : "l"(p));
    return a;
}
#define CP_ASYNC16(smem, gptr) \
    asm volatile("cp.async.cg.shared.global [%0], [%1], 16;" \
                 :: "r"(smem), "l"(gptr) : "memory")
#define CP_COMMIT() asm volatile("cp.async.commit_group;" ::: "memory")
#define CP_WAIT(N)  asm volatile("cp.async.wait_group %0;" :: "n"(N) : "memory")

__device__ __forceinline__ uint32_t packh2(float a, float b) {
    __half2 h = __floats2half2_rn(a, b);
    return *reinterpret_cast<uint32_t*>(&h);
}
__device__ __forceinline__ void mma_f16(float* c, const uint32_t* a,
                                        const uint32_t* b) {
    asm volatile(
        "mma.sync.aligned.m16n8k16.row.col.f32.f16.f16.f32 "
        "{%0,%1,%2,%3}, {%4,%5,%6,%7}, {%8,%9}, {%0,%1,%2,%3};"
        : "+f"(c[0]), "+f"(c[1]), "+f"(c[2]), "+f"(c[3])
        : "r"(a[0]), "r"(a[1]), "r"(a[2]), "r"(a[3]), "r"(b[0]), "r"(b[1]));
}

// ---------------------------------------------------------------------------
// Prepass: pack fp32 into k-paired half2 (R12-proven).
// ---------------------------------------------------------------------------
__global__ __launch_bounds__(256) void pack_flat(
    const float2* __restrict__ in, uint32_t* __restrict__ out, int n2)
{
    int i = blockIdx.x * 256 + threadIdx.x;
    if (i < n2) {
        float2 v = in[i];
        out[i] = packh2(v.x, v.y);
    }
}
__global__ __launch_bounds__(256) void pack_w(
    const float* __restrict__ in, uint32_t* __restrict__ out, int N)
{
    int n = blockIdx.x * 256 + threadIdx.x;
    int kp = blockIdx.y;
    float a = in[(size_t)(2 * kp) * N + n];
    float b = in[(size_t)(2 * kp + 1) * N + n];
    out[(size_t)kp * N + n] = packh2(a, b);
}

// ---------------------------------------------------------------------------
// fp16 mma.sync GEMM (m16n8k16) — R12-proven, unchanged.
// ---------------------------------------------------------------------------
#define GK2 2048
#define NT 128
#define AS_STRIDE 20
#define BS_STRIDE 136
#define AS_U (128 * AS_STRIDE)
#define BS_U (16 * BS_STRIDE)
#define STAGE_U (AS_U + BS_U)
#define NSTAGE 3
#define GSMEM_BYTES (NSTAGE * STAGE_U * 4)

__global__ __launch_bounds__(256, 2) void gemm_h(
    const uint32_t* __restrict__ A,
    const uint32_t* __restrict__ B0, float* __restrict__ C0,
    const float* __restrict__ bias0, int N0, int NX0,
    const uint32_t* __restrict__ B1, float* __restrict__ C1, int N1)
{
    extern __shared__ uint32_t sh[];
    const uint32_t smb = smem_u32(sh);

    const int tid = threadIdx.x;
    const int wid = tid >> 5;
    const int lane = tid & 31;
    const int gid = lane >> 2;
    const int tig = lane & 3;
    const int warp_m = (wid & 1) * 64;
    const int warp_n = (wid >> 1) * 32;

    const int by = blockIdx.y;
    int bx = blockIdx.x;

    const uint32_t* B; float* C; const float* bias; int N;
    if (bx < NX0) { B = B0; C = C0; bias = bias0; N = N0; }
    else          { B = B1; C = C1; bias = nullptr; N = N1; bx -= NX0; }

    const uint32_t* Ab = A + (size_t)by * 128 * GK2;
    const uint32_t* Bb = B + (size_t)bx * 128;

    auto load_tile = [&](int kt, int s) {
        const uint32_t* ag = Ab + kt * 16;
        const uint32_t* bg = Bb + (size_t)(kt * 16) * N;
        uint32_t ab = smb + 4 * (s * STAGE_U);
        uint32_t bb = ab + 4 * AS_U;
#pragma unroll
        for (int i = 0; i < 2; i++) {
            int id = tid + i * 256;
            int r = id >> 2, c = (id & 3) * 4;
            CP_ASYNC16(ab + (r * AS_STRIDE + c) * 4, ag + (size_t)r * GK2 + c);
        }
#pragma unroll
        for (int i = 0; i < 2; i++) {
            int id = tid + i * 256;
            int r = id >> 5, c = (id & 31) * 4;
            CP_ASYNC16(bb + (r * BS_STRIDE + c) * 4, bg + (size_t)r * N + c);
        }
        CP_COMMIT();
    };

    float acc[4][4][4];
#pragma unroll
    for (int i = 0; i < 4; i++)
#pragma unroll
        for (int j = 0; j < 4; j++)
#pragma unroll
            for (int k = 0; k < 4; k++) acc[i][j][k] = 0.f;

    load_tile(0, 0);
    load_tile(1, 1);

    for (int kt = 0; kt < NT; kt++) {
        if (kt < NT - 1) { CP_WAIT(1); } else { CP_WAIT(0); }
        __syncthreads();
        if (kt + 2 < NT) load_tile(kt + 2, (kt + 2) % NSTAGE);

        const uint32_t* as = sh + (kt % NSTAGE) * STAGE_U;
        const uint32_t* bs = as + AS_U;

#pragma unroll
        for (int ks = 0; ks < 2; ks++) {
            const int k0 = ks * 8;
            uint32_t afr[4][4];
#pragma unroll
            for (int mf = 0; mf < 4; mf++) {
                const uint32_t* ap = as + (warp_m + mf * 16 + gid) * AS_STRIDE + k0 + tig;
                afr[mf][0] = ap[0];
                afr[mf][1] = ap[8 * AS_STRIDE];
                afr[mf][2] = ap[4];
                afr[mf][3] = ap[8 * AS_STRIDE + 4];
            }
            uint32_t bfr[4][2];
#pragma unroll
            for (int nf = 0; nf < 4; nf++) {
                const uint32_t* bp = bs + (k0 + tig) * BS_STRIDE + warp_n + nf * 8 + gid;
                bfr[nf][0] = bp[0];
                bfr[nf][1] = bp[4 * BS_STRIDE];
            }
#pragma unroll
            for (int mf = 0; mf < 4; mf++)
#pragma unroll
                for (int nf = 0; nf < 4; nf++)
                    mma_f16(acc[mf][nf], afr[mf], bfr[nf]);
        }
    }

#pragma unroll
    for (int mf = 0; mf < 4; mf++) {
#pragma unroll
        for (int nf = 0; nf < 4; nf++) {
            int row0 = by * 128 + warp_m + mf * 16 + gid;
            int col  = bx * 128 + warp_n + nf * 8 + tig * 2;
            float b0 = 0.f, b1 = 0.f;
            if (bias) { b0 = __ldg(bias + col); b1 = __ldg(bias + col + 1); }
            float2 v0 = make_float2(acc[mf][nf][0] + b0, acc[mf][nf][1] + b1);
            float2 v1 = make_float2(acc[mf][nf][2] + b0, acc[mf][nf][3] + b1);
            *(float2*)(C + (size_t)row0 * N + col) = v0;
            *(float2*)(C + (size_t)(row0 + 8) * N + col) = v1;
        }
    }
}

// ---------------------------------------------------------------------------
// fp16 tensor-core causal GQA flash attention (m16n8k16).
// Grid (NHEAD, T/64). Block 128 = 4 warps x 16 query rows.
// Smem u32: Ksh[64 keys][68]   (kp_d-major per key; 68 % 32 == 4)
//           Vsh[32 kp_key][136] (d-major per key-pair; 136 % 32 == 8)
//           Psh[4][16 rows][36] (kp_key-major per row; 36 % 32 == 4)
// ---------------------------------------------------------------------------
#define KSTR 68
#define VSTR 136
#define PSTR 36
#define ATT_SMEM_UINTS (64 * KSTR + 32 * VSTR + 4 * 16 * PSTR)  // 11008
#define ATT_SMEM_BYTES (ATT_SMEM_UINTS * 4)                     // 44032

__global__ __launch_bounds__(128, 2) void attn_h(
    const float* __restrict__ q, const float* __restrict__ kv,
    uint32_t* __restrict__ ctxh)
{
    const int h  = blockIdx.x;
    const int qt = blockIdx.y;
    const int g  = h >> 2;

    extern __shared__ uint32_t smu[];
    uint32_t* Ksh = smu;                 // [64][KSTR]
    uint32_t* Vsh = Ksh + 64 * KSTR;     // [32][VSTR]
    uint32_t* Psh = Vsh + 32 * VSTR;     // [4][16][PSTR]

    const int tid  = threadIdx.x;
    const int wid  = tid >> 5;
    const int lane = tid & 31;
    const int gid  = lane >> 2;
    const int tig  = lane & 3;

    uint32_t* Pw = Psh + wid * 16 * PSTR;

    const int r0 = qt * 64 + wid * 16;
    const int rowg0 = r0 + gid;
    const int rowg1 = r0 + gid + 8;

    // Q fragments (fp16 packed), 8 k16 steps covering HD=128 (64 kp)
    uint32_t qf[8][4];
    {
        const float* qb = q + (size_t)rowg0 * D_DIM + h * HDIM;
#pragma unroll
        for (int kf = 0; kf < 8; kf++) {
            int kp0 = kf * 8 + tig;
            int kp1 = kp0 + 4;
            qf[kf][0] = packh2(qb[2 * kp0], qb[2 * kp0 + 1]);
            qf[kf][1] = packh2(qb[8 * D_DIM + 2 * kp0], qb[8 * D_DIM + 2 * kp0 + 1]);
            qf[kf][2] = packh2(qb[2 * kp1], qb[2 * kp1 + 1]);
            qf[kf][3] = packh2(qb[8 * D_DIM + 2 * kp1], qb[8 * D_DIM + 2 * kp1 + 1]);
        }
    }

    float o[16][4];
#pragma unroll
    for (int nf = 0; nf < 16; nf++)
#pragma unroll
        for (int j = 0; j < 4; j++) o[nf][j] = 0.f;
    float m0 = -1e30f, m1 = -1e30f, l0 = 0.f, l1 = 0.f;
    const float scale = 0.08838834764831845f;

    for (int kt = 0; kt <= qt; kt++) {
        __syncthreads();
        const float* kvb = kv + (size_t)(kt * 64) * KVDIM + g * (2 * HDIM);
        // K: 64 keys x 128 d -> Ksh[key][kp_d], pack along d
        for (int i = tid; i < 64 * 32; i += 128) {
            int row = i >> 5;
            int c4  = (i & 31) * 4;
            float4 kk = *(const float4*)(kvb + (size_t)row * KVDIM + c4);
            uint32_t* kp = Ksh + row * KSTR + (c4 >> 1);
            kp[0] = packh2(kk.x, kk.y);
            kp[1] = packh2(kk.z, kk.w);
        }
        // V: pack across key pairs -> Vsh[kp_key][d]
        for (int i = tid; i < 32 * 32; i += 128) {
            int kpr = i >> 5;
            int c4  = (i & 31) * 4;
            float4 v0 = *(const float4*)(kvb + (size_t)(2 * kpr) * KVDIM + HDIM + c4);
            float4 v1 = *(const float4*)(kvb + (size_t)(2 * kpr + 1) * KVDIM + HDIM + c4);
            uint32_t* vp = Vsh + kpr * VSTR + c4;
            vp[0] = packh2(v0.x, v1.x);
            vp[1] = packh2(v0.y, v1.y);
            vp[2] = packh2(v0.z, v1.z);
            vp[3] = packh2(v0.w, v1.w);
        }
        __syncthreads();

        // ---- S = Q @ K^T : 8 k16 steps x 8 nf ----
        float sa[8][4];
#pragma unroll
        for (int nf = 0; nf < 8; nf++)
#pragma unroll
            for (int j = 0; j < 4; j++) sa[nf][j] = 0.f;

#pragma unroll
        for (int kf = 0; kf < 8; kf++) {
#pragma unroll
            for (int nf = 0; nf < 8; nf++) {
                const uint32_t* kp = Ksh + (nf * 8 + gid) * KSTR + kf * 8 + tig;
                uint32_t bfr[2] = { kp[0], kp[4] };
                mma_f16(sa[nf], qf[kf], bfr);
            }
        }

        // ---- scale + causal mask ----
        const bool diag = (kt == qt);
#pragma unroll
        for (int nf = 0; nf < 8; nf++) {
            int c = kt * 64 + nf * 8 + 2 * tig;
#pragma unroll
            for (int j = 0; j < 4; j++) sa[nf][j] *= scale;
            if (diag) {
                if (c     > rowg0) sa[nf][0] = -1e30f;
                if (c + 1 > rowg0) sa[nf][1] = -1e30f;
                if (c     > rowg1) sa[nf][2] = -1e30f;
                if (c + 1 > rowg1) sa[nf][3] = -1e30f;
            }
        }

        // ---- row max ----
        float mx0 = -1e30f, mx1 = -1e30f;
#pragma unroll
        for (int nf = 0; nf < 8; nf++) {
            mx0 = fmaxf(mx0, fmaxf(sa[nf][0], sa[nf][1]));
            mx1 = fmaxf(mx1, fmaxf(sa[nf][2], sa[nf][3]));
        }
        mx0 = fmaxf(mx0, __shfl_xor_sync(0xffffffff, mx0, 1));
        mx0 = fmaxf(mx0, __shfl_xor_sync(0xffffffff, mx0, 2));
        mx1 = fmaxf(mx1, __shfl_xor_sync(0xffffffff, mx1, 1));
        mx1 = fmaxf(mx1, __shfl_xor_sync(0xffffffff, mx1, 2));

        float mn0 = fmaxf(m0, mx0), mn1 = fmaxf(m1, mx1);
        float al0 = __expf(m0 - mn0), al1 = __expf(m1 - mn1);

        // ---- exp, P to smem (half2 of adjacent keys), row sum ----
        float s0 = 0.f, s1 = 0.f;
#pragma unroll
        for (int nf = 0; nf < 8; nf++) {
            float p00 = __expf(sa[nf][0] - mn0);
            float p01 = __expf(sa[nf][1] - mn0);
            float p10 = __expf(sa[nf][2] - mn1);
            float p11 = __expf(sa[nf][3] - mn1);
            s0 += p00 + p01;
            s1 += p10 + p11;
            int kp = nf * 4 + tig;
            Pw[gid * PSTR + kp]       = packh2(p00, p01);
            Pw[(gid + 8) * PSTR + kp] = packh2(p10, p11);
        }
        s0 += __shfl_xor_sync(0xffffffff, s0, 1);
        s0 += __shfl_xor_sync(0xffffffff, s0, 2);
        s1 += __shfl_xor_sync(0xffffffff, s1, 1);
        s1 += __shfl_xor_sync(0xffffffff, s1, 2);

        l0 = l0 * al0 + s0;
        l1 = l1 * al1 + s1;
        m0 = mn0; m1 = mn1;

        // ---- rescale O ----
#pragma unroll
        for (int nf = 0; nf < 16; nf++) {
            o[nf][0] *= al0; o[nf][1] *= al0;
            o[nf][2] *= al1; o[nf][3] *= al1;
        }
        __syncwarp();

        // ---- O += P @ V : 4 k16 steps x 16 nf ----
#pragma unroll
        for (int kf = 0; kf < 4; kf++) {
            uint32_t pa[4];
            pa[0] = Pw[gid * PSTR + kf * 8 + tig];
            pa[1] = Pw[(gid + 8) * PSTR + kf * 8 + tig];
            pa[2] = Pw[gid * PSTR + kf * 8 + tig + 4];
            pa[3] = Pw[(gid + 8) * PSTR + kf * 8 + tig + 4];
#pragma unroll
            for (int nf = 0; nf < 16; nf++) {
                const uint32_t* vp = Vsh + (kf * 8 + tig) * VSTR + nf * 8 + gid;
                uint32_t bfr[2] = { vp[0], vp[4 * VSTR] };
                mma_f16(o[nf], pa, bfr);
            }
        }
        __syncwarp();
    }

    // Normalize + write half2-packed ctx
    float inv0 = 1.0f / l0, inv1 = 1.0f / l1;
    uint32_t* cb = ctxh + (size_t)rowg0 * (D_DIM / 2) + h * (HDIM / 2);
#pragma unroll
    for (int nf = 0; nf < 16; nf++) {
        int cp = nf * 4 + tig;
        cb[cp] = packh2(o[nf][0] * inv0, o[nf][1] * inv0);
        cb[8 * (D_DIM / 2) + cp] = packh2(o[nf][2] * inv1, o[nf][3] * inv1);
    }
}

// ---------------------------------------------------------------------------
// Launch
// ---------------------------------------------------------------------------
extern "C" void kernel_launch(void* const* d_in, const int* in_sizes, int n_in,
                              void* d_out, int out_size)
{
    const float* x   = (const float*)d_in[0];
    const float* Wq  = (const float*)d_in[1];
    const float* Wkv = (const float*)d_in[2];
    const float* Wo  = (const float*)d_in[3];
    const float* bo  = (const float*)d_in[4];
    float* out = (float*)d_out;

    float *qp, *kvp;
    uint32_t *ctxh, *xh, *wqh, *wkvh, *woh;
    cudaGetSymbolAddress((void**)&qp,   g_q);
    cudaGetSymbolAddress((void**)&kvp,  g_kv);
    cudaGetSymbolAddress((void**)&ctxh, g_ctxh);
    cudaGetSymbolAddress((void**)&xh,   g_xh);
    cudaGetSymbolAddress((void**)&wqh,  g_wqh);
    cudaGetSymbolAddress((void**)&wkvh, g_wkvh);
    cudaGetSymbolAddress((void**)&woh,  g_woh);

    cudaFuncSetAttribute(attn_h,
                         cudaFuncAttributeMaxDynamicSharedMemorySize,
                         ATT_SMEM_BYTES);
    cudaFuncSetAttribute(gemm_h,
                         cudaFuncAttributeMaxDynamicSharedMemorySize,
                         GSMEM_BYTES);

    // Prepass: pack operands to fp16
    pack_flat<<<T_LEN * D_DIM / 2 / 256, 256>>>(
        (const float2*)x, xh, T_LEN * D_DIM / 2);
    pack_w<<<dim3(D_DIM / 256, D_DIM / 2), 256>>>(Wq, wqh, D_DIM);
    pack_w<<<dim3(KVDIM / 256, D_DIM / 2), 256>>>(Wkv, wkvh, KVDIM);
    pack_w<<<dim3(D_DIM / 256, D_DIM / 2), 256>>>(Wo, woh, D_DIM);

    // 1+2) fused: q = x@Wq (bx<32), kv = x@Wkv (bx>=32)
    gemm_h<<<dim3(D_DIM / 128 + KVDIM / 128, T_LEN / 128), 256, GSMEM_BYTES>>>(
        xh, wqh, qp, nullptr, D_DIM, D_DIM / 128, wkvh, kvp, KVDIM);
    // 3) attention (fp16 mma, writes half2-packed ctx)
    attn_h<<<dim3(NHEAD, T_LEN / 64), 128, ATT_SMEM_BYTES>>>(qp, kvp, ctxh);
    // 4) out = ctx @ Wo + bo
    gemm_h<<<dim3(D_DIM / 128, T_LEN / 128), 256, GSMEM_BYTES>>>(
        ctxh, woh, out, bo, D_DIM, D_DIM / 128, woh, out, D_DIM);

    (void)in_sizes; (void)n_in; (void)out_size;
}

// round 14
// speedup vs baseline: 1.8575x; 1.0134x over previous
#include <cuda_runtime.h>
#include <cuda_fp16.h>
#include <cuda_bf16.h>
#include <cstdint>
#include <math.h>

// Problem constants
#define T_LEN 2048
#define D_DIM 4096
#define NHEAD 32
#define NGRP 8
#define HDIM 128
#define KVDIM 2048   // 2 * HDIM * NGRP

// Scratch (no cudaMalloc allowed)
__device__ float    g_q[T_LEN * D_DIM];          // 32 MB f32
__device__ float    g_kv[T_LEN * KVDIM];         // 16 MB f32
__device__ uint32_t g_ctxh[T_LEN * D_DIM / 2];   // 16 MB half2-packed ctx
__device__ uint32_t g_xh[T_LEN * D_DIM / 2];     // 16 MB x  half2 [T][D/2]
__device__ uint32_t g_wqh[D_DIM / 2 * D_DIM];    // 32 MB Wq  kp-major [K/2][N]
__device__ uint32_t g_wkvh[D_DIM / 2 * KVDIM];   // 16 MB Wkv [K/2][N]
__device__ uint32_t g_woh[D_DIM / 2 * D_DIM];    // 32 MB Wo  [K/2][N]

// ---------------------------------------------------------------------------
// Helpers
// ---------------------------------------------------------------------------
__device__ __forceinline__ uint32_t smem_u32(const void* p) {
    uint32_t a;
    asm("{ .reg .u64 t; cvta.to.shared.u64 t, %1; cvt.u32.u64 %0, t; }"
        : "=r"(a) : "l"(p));
    return a;
}
#define CP_ASYNC16(smem, gptr) \
    asm volatile("cp.async.cg.shared.global [%0], [%1], 16;" \
                 :: "r"(smem), "l"(gptr) : "memory")
#define CP_COMMIT() asm volatile("cp.async.commit_group;" ::: "memory")
#define CP_WAIT(N)  asm volatile("cp.async.wait_group %0;" :: "n"(N) : "memory")
#define LDSM_X4(r0, r1, r2, r3, addr) \
    asm volatile("ldmatrix.sync.aligned.m8n8.x4.shared.b16 {%0,%1,%2,%3}, [%4];" \
                 : "=r"(r0), "=r"(r1), "=r"(r2), "=r"(r3) : "r"(addr))

__device__ __forceinline__ uint32_t packh2(float a, float b) {
    __half2 h = __floats2half2_rn(a, b);
    return *reinterpret_cast<uint32_t*>(&h);
}
__device__ __forceinline__ void mma_f16(float* c, const uint32_t* a,
                                        const uint32_t* b) {
    asm volatile(
        "mma.sync.aligned.m16n8k16.row.col.f32.f16.f16.f32 "
        "{%0,%1,%2,%3}, {%4,%5,%6,%7}, {%8,%9}, {%0,%1,%2,%3};"
        : "+f"(c[0]), "+f"(c[1]), "+f"(c[2]), "+f"(c[3])
        : "r"(a[0]), "r"(a[1]), "r"(a[2]), "r"(a[3]), "r"(b[0]), "r"(b[1]));
}

// ---------------------------------------------------------------------------
// Prepass: pack fp32 into k-paired half2 (R12-proven).
// ---------------------------------------------------------------------------
__global__ __launch_bounds__(256) void pack_flat(
    const float2* __restrict__ in, uint32_t* __restrict__ out, int n2)
{
    int i = blockIdx.x * 256 + threadIdx.x;
    if (i < n2) {
        float2 v = in[i];
        out[i] = packh2(v.x, v.y);
    }
}
__global__ __launch_bounds__(256) void pack_w(
    const float* __restrict__ in, uint32_t* __restrict__ out, int N)
{
    int n = blockIdx.x * 256 + threadIdx.x;
    int kp = blockIdx.y;
    float a = in[(size_t)(2 * kp) * N + n];
    float b = in[(size_t)(2 * kp + 1) * N + n];
    out[(size_t)kp * N + n] = packh2(a, b);
}

// ---------------------------------------------------------------------------
// fp16 mma.sync GEMM (m16n8k16), A-fragments via ldmatrix.x4.
// C[M,N] = A[M,K] @ B[K,N] (+bias), dual-output fusion via NX0 split.
// BM=128, BN=128, BK=32 elem (16 kp), 256 threads (8 warps 2x4), warp 64x32.
// 3-stage cp.async ring, ONE barrier per tile.
// ---------------------------------------------------------------------------
#define GK2 2048
#define NT 128
#define AS_STRIDE 20
#define BS_STRIDE 136
#define AS_U (128 * AS_STRIDE)
#define BS_U (16 * BS_STRIDE)
#define STAGE_U (AS_U + BS_U)
#define NSTAGE 3
#define GSMEM_BYTES (NSTAGE * STAGE_U * 4)

__global__ __launch_bounds__(256, 2) void gemm_h(
    const uint32_t* __restrict__ A,
    const uint32_t* __restrict__ B0, float* __restrict__ C0,
    const float* __restrict__ bias0, int N0, int NX0,
    const uint32_t* __restrict__ B1, float* __restrict__ C1, int N1)
{
    extern __shared__ uint32_t sh[];
    const uint32_t smb = smem_u32(sh);

    const int tid = threadIdx.x;
    const int wid = tid >> 5;
    const int lane = tid & 31;
    const int gid = lane >> 2;
    const int tig = lane & 3;
    const int warp_m = (wid & 1) * 64;
    const int warp_n = (wid >> 1) * 32;

    const int by = blockIdx.y;
    int bx = blockIdx.x;

    const uint32_t* B; float* C; const float* bias; int N;
    if (bx < NX0) { B = B0; C = C0; bias = bias0; N = N0; }
    else          { B = B1; C = C1; bias = nullptr; N = N1; bx -= NX0; }

    const uint32_t* Ab = A + (size_t)by * 128 * GK2;
    const uint32_t* Bb = B + (size_t)bx * 128;

    auto load_tile = [&](int kt, int s) {
        const uint32_t* ag = Ab + kt * 16;
        const uint32_t* bg = Bb + (size_t)(kt * 16) * N;
        uint32_t ab = smb + 4 * (s * STAGE_U);
        uint32_t bb = ab + 4 * AS_U;
#pragma unroll
        for (int i = 0; i < 2; i++) {
            int id = tid + i * 256;
            int r = id >> 2, c = (id & 3) * 4;
            CP_ASYNC16(ab + (r * AS_STRIDE + c) * 4, ag + (size_t)r * GK2 + c);
        }
#pragma unroll
        for (int i = 0; i < 2; i++) {
            int id = tid + i * 256;
            int r = id >> 5, c = (id & 31) * 4;
            CP_ASYNC16(bb + (r * BS_STRIDE + c) * 4, bg + (size_t)r * N + c);
        }
        CP_COMMIT();
    };

    // ldmatrix lane address components for A fragments
    const int lmr = lane & 15;          // row within 16-row tile
    const int lmc = (lane >> 4) * 4;    // kp column offset (0 or 4)

    float acc[4][4][4];
#pragma unroll
    for (int i = 0; i < 4; i++)
#pragma unroll
        for (int j = 0; j < 4; j++)
#pragma unroll
            for (int k = 0; k < 4; k++) acc[i][j][k] = 0.f;

    load_tile(0, 0);
    load_tile(1, 1);

    for (int kt = 0; kt < NT; kt++) {
        if (kt < NT - 1) { CP_WAIT(1); } else { CP_WAIT(0); }
        __syncthreads();
        if (kt + 2 < NT) load_tile(kt + 2, (kt + 2) % NSTAGE);

        const uint32_t sbase = smb + 4 * ((kt % NSTAGE) * STAGE_U);
        const uint32_t* bs = sh + (kt % NSTAGE) * STAGE_U + AS_U;

#pragma unroll
        for (int ks = 0; ks < 2; ks++) {
            const int k0 = ks * 8;
            uint32_t afr[4][4];
#pragma unroll
            for (int mf = 0; mf < 4; mf++) {
                uint32_t ad = sbase +
                    4 * ((warp_m + mf * 16 + lmr) * AS_STRIDE + k0 + lmc);
                LDSM_X4(afr[mf][0], afr[mf][1], afr[mf][2], afr[mf][3], ad);
            }
            uint32_t bfr[4][2];
#pragma unroll
            for (int nf = 0; nf < 4; nf++) {
                const uint32_t* bp = bs + (k0 + tig) * BS_STRIDE + warp_n + nf * 8 + gid;
                bfr[nf][0] = bp[0];
                bfr[nf][1] = bp[4 * BS_STRIDE];
            }
#pragma unroll
            for (int mf = 0; mf < 4; mf++)
#pragma unroll
                for (int nf = 0; nf < 4; nf++)
                    mma_f16(acc[mf][nf], afr[mf], bfr[nf]);
        }
    }

#pragma unroll
    for (int mf = 0; mf < 4; mf++) {
#pragma unroll
        for (int nf = 0; nf < 4; nf++) {
            int row0 = by * 128 + warp_m + mf * 16 + gid;
            int col  = bx * 128 + warp_n + nf * 8 + tig * 2;
            float b0 = 0.f, b1 = 0.f;
            if (bias) { b0 = __ldg(bias + col); b1 = __ldg(bias + col + 1); }
            float2 v0 = make_float2(acc[mf][nf][0] + b0, acc[mf][nf][1] + b1);
            float2 v1 = make_float2(acc[mf][nf][2] + b0, acc[mf][nf][3] + b1);
            *(float2*)(C + (size_t)row0 * N + col) = v0;
            *(float2*)(C + (size_t)(row0 + 8) * N + col) = v1;
        }
    }
}

// ---------------------------------------------------------------------------
// fp16 tensor-core causal GQA flash attention (m16n8k16), R13-proven.
// P-fragments in the PV loop now load via ldmatrix.x4.
// ---------------------------------------------------------------------------
#define KSTR 68
#define VSTR 136
#define PSTR 36
#define ATT_SMEM_UINTS (64 * KSTR + 32 * VSTR + 4 * 16 * PSTR)
#define ATT_SMEM_BYTES (ATT_SMEM_UINTS * 4)

__global__ __launch_bounds__(128, 2) void attn_h(
    const float* __restrict__ q, const float* __restrict__ kv,
    uint32_t* __restrict__ ctxh)
{
    const int h  = blockIdx.x;
    const int qt = blockIdx.y;
    const int g  = h >> 2;

    extern __shared__ uint32_t smu[];
    uint32_t* Ksh = smu;
    uint32_t* Vsh = Ksh + 64 * KSTR;
    uint32_t* Psh = Vsh + 32 * VSTR;

    const int tid  = threadIdx.x;
    const int wid  = tid >> 5;
    const int lane = tid & 31;
    const int gid  = lane >> 2;
    const int tig  = lane & 3;

    uint32_t* Pw = Psh + wid * 16 * PSTR;
    const uint32_t pw_base = smem_u32(Pw);
    const int lmr = lane & 15;
    const int lmc = (lane >> 4) * 4;

    const int r0 = qt * 64 + wid * 16;
    const int rowg0 = r0 + gid;
    const int rowg1 = r0 + gid + 8;

    uint32_t qf[8][4];
    {
        const float* qb = q + (size_t)rowg0 * D_DIM + h * HDIM;
#pragma unroll
        for (int kf = 0; kf < 8; kf++) {
            int kp0 = kf * 8 + tig;
            int kp1 = kp0 + 4;
            qf[kf][0] = packh2(qb[2 * kp0], qb[2 * kp0 + 1]);
            qf[kf][1] = packh2(qb[8 * D_DIM + 2 * kp0], qb[8 * D_DIM + 2 * kp0 + 1]);
            qf[kf][2] = packh2(qb[2 * kp1], qb[2 * kp1 + 1]);
            qf[kf][3] = packh2(qb[8 * D_DIM + 2 * kp1], qb[8 * D_DIM + 2 * kp1 + 1]);
        }
    }

    float o[16][4];
#pragma unroll
    for (int nf = 0; nf < 16; nf++)
#pragma unroll
        for (int j = 0; j < 4; j++) o[nf][j] = 0.f;
    float m0 = -1e30f, m1 = -1e30f, l0 = 0.f, l1 = 0.f;
    const float scale = 0.08838834764831845f;

    for (int kt = 0; kt <= qt; kt++) {
        __syncthreads();
        const float* kvb = kv + (size_t)(kt * 64) * KVDIM + g * (2 * HDIM);
        for (int i = tid; i < 64 * 32; i += 128) {
            int row = i >> 5;
            int c4  = (i & 31) * 4;
            float4 kk = *(const float4*)(kvb + (size_t)row * KVDIM + c4);
            uint32_t* kp = Ksh + row * KSTR + (c4 >> 1);
            kp[0] = packh2(kk.x, kk.y);
            kp[1] = packh2(kk.z, kk.w);
        }
        for (int i = tid; i < 32 * 32; i += 128) {
            int kpr = i >> 5;
            int c4  = (i & 31) * 4;
            float4 v0 = *(const float4*)(kvb + (size_t)(2 * kpr) * KVDIM + HDIM + c4);
            float4 v1 = *(const float4*)(kvb + (size_t)(2 * kpr + 1) * KVDIM + HDIM + c4);
            uint32_t* vp = Vsh + kpr * VSTR + c4;
            vp[0] = packh2(v0.x, v1.x);
            vp[1] = packh2(v0.y, v1.y);
            vp[2] = packh2(v0.z, v1.z);
            vp[3] = packh2(v0.w, v1.w);
        }
        __syncthreads();

        float sa[8][4];
#pragma unroll
        for (int nf = 0; nf < 8; nf++)
#pragma unroll
            for (int j = 0; j < 4; j++) sa[nf][j] = 0.f;

#pragma unroll
        for (int kf = 0; kf < 8; kf++) {
#pragma unroll
            for (int nf = 0; nf < 8; nf++) {
                const uint32_t* kp = Ksh + (nf * 8 + gid) * KSTR + kf * 8 + tig;
                uint32_t bfr[2] = { kp[0], kp[4] };
                mma_f16(sa[nf], qf[kf], bfr);
            }
        }

        const bool diag = (kt == qt);
#pragma unroll
        for (int nf = 0; nf < 8; nf++) {
            int c = kt * 64 + nf * 8 + 2 * tig;
#pragma unroll
            for (int j = 0; j < 4; j++) sa[nf][j] *= scale;
            if (diag) {
                if (c     > rowg0) sa[nf][0] = -1e30f;
                if (c + 1 > rowg0) sa[nf][1] = -1e30f;
                if (c     > rowg1) sa[nf][2] = -1e30f;
                if (c + 1 > rowg1) sa[nf][3] = -1e30f;
            }
        }

        float mx0 = -1e30f, mx1 = -1e30f;
#pragma unroll
        for (int nf = 0; nf < 8; nf++) {
            mx0 = fmaxf(mx0, fmaxf(sa[nf][0], sa[nf][1]));
            mx1 = fmaxf(mx1, fmaxf(sa[nf][2], sa[nf][3]));
        }
        mx0 = fmaxf(mx0, __shfl_xor_sync(0xffffffff, mx0, 1));
        mx0 = fmaxf(mx0, __shfl_xor_sync(0xffffffff, mx0, 2));
        mx1 = fmaxf(mx1, __shfl_xor_sync(0xffffffff, mx1, 1));
        mx1 = fmaxf(mx1, __shfl_xor_sync(0xffffffff, mx1, 2));

        float mn0 = fmaxf(m0, mx0), mn1 = fmaxf(m1, mx1);
        float al0 = __expf(m0 - mn0), al1 = __expf(m1 - mn1);

        float s0 = 0.f, s1 = 0.f;
#pragma unroll
        for (int nf = 0; nf < 8; nf++) {
            float p00 = __expf(sa[nf][0] - mn0);
            float p01 = __expf(sa[nf][1] - mn0);
            float p10 = __expf(sa[nf][2] - mn1);
            float p11 = __expf(sa[nf][3] - mn1);
            s0 += p00 + p01;
            s1 += p10 + p11;
            int kp = nf * 4 + tig;
            Pw[gid * PSTR + kp]       = packh2(p00, p01);
            Pw[(gid + 8) * PSTR + kp] = packh2(p10, p11);
        }
        s0 += __shfl_xor_sync(0xffffffff, s0, 1);
        s0 += __shfl_xor_sync(0xffffffff, s0, 2);
        s1 += __shfl_xor_sync(0xffffffff, s1, 1);
        s1 += __shfl_xor_sync(0xffffffff, s1, 2);

        l0 = l0 * al0 + s0;
        l1 = l1 * al1 + s1;
        m0 = mn0; m1 = mn1;

#pragma unroll
        for (int nf = 0; nf < 16; nf++) {
            o[nf][0] *= al0; o[nf][1] *= al0;
            o[nf][2] *= al1; o[nf][3] *= al1;
        }
        __syncwarp();

#pragma unroll
        for (int kf = 0; kf < 4; kf++) {
            uint32_t pa[4];
            uint32_t pad = pw_base + 4 * (lmr * PSTR + kf * 8 + lmc);
            LDSM_X4(pa[0], pa[1], pa[2], pa[3], pad);
#pragma unroll
            for (int nf = 0; nf < 16; nf++) {
                const uint32_t* vp = Vsh + (kf * 8 + tig) * VSTR + nf * 8 + gid;
                uint32_t bfr[2] = { vp[0], vp[4 * VSTR] };
                mma_f16(o[nf], pa, bfr);
            }
        }
        __syncwarp();
    }

    float inv0 = 1.0f / l0, inv1 = 1.0f / l1;
    uint32_t* cb = ctxh + (size_t)rowg0 * (D_DIM / 2) + h * (HDIM / 2);
#pragma unroll
    for (int nf = 0; nf < 16; nf++) {
        int cp = nf * 4 + tig;
        cb[cp] = packh2(o[nf][0] * inv0, o[nf][1] * inv0);
        cb[8 * (D_DIM / 2) + cp] = packh2(o[nf][2] * inv1, o[nf][3] * inv1);
    }
}

// ---------------------------------------------------------------------------
// Launch
// ---------------------------------------------------------------------------
extern "C" void kernel_launch(void* const* d_in, const int* in_sizes, int n_in,
                              void* d_out, int out_size)
{
    const float* x   = (const float*)d_in[0];
    const float* Wq  = (const float*)d_in[1];
    const float* Wkv = (const float*)d_in[2];
    const float* Wo  = (const float*)d_in[3];
    const float* bo  = (const float*)d_in[4];
    float* out = (float*)d_out;

    float *qp, *kvp;
    uint32_t *ctxh, *xh, *wqh, *wkvh, *woh;
    cudaGetSymbolAddress((void**)&qp,   g_q);
    cudaGetSymbolAddress((void**)&kvp,  g_kv);
    cudaGetSymbolAddress((void**)&ctxh, g_ctxh);
    cudaGetSymbolAddress((void**)&xh,   g_xh);
    cudaGetSymbolAddress((void**)&wqh,  g_wqh);
    cudaGetSymbolAddress((void**)&wkvh, g_wkvh);
    cudaGetSymbolAddress((void**)&woh,  g_woh);

    cudaFuncSetAttribute(attn_h,
                         cudaFuncAttributeMaxDynamicSharedMemorySize,
                         ATT_SMEM_BYTES);
    cudaFuncSetAttribute(gemm_h,
                         cudaFuncAttributeMaxDynamicSharedMemorySize,
                         GSMEM_BYTES);

    // Prepass: pack operands to fp16
    pack_flat<<<T_LEN * D_DIM / 2 / 256, 256>>>(
        (const float2*)x, xh, T_LEN * D_DIM / 2);
    pack_w<<<dim3(D_DIM / 256, D_DIM / 2), 256>>>(Wq, wqh, D_DIM);
    pack_w<<<dim3(KVDIM / 256, D_DIM / 2), 256>>>(Wkv, wkvh, KVDIM);
    pack_w<<<dim3(D_DIM / 256, D_DIM / 2), 256>>>(Wo, woh, D_DIM);

    // 1+2) fused: q = x@Wq (bx<32), kv = x@Wkv (bx>=32)
    gemm_h<<<dim3(D_DIM / 128 + KVDIM / 128, T_LEN / 128), 256, GSMEM_BYTES>>>(
        xh, wqh, qp, nullptr, D_DIM, D_DIM / 128, wkvh, kvp, KVDIM);
    // 3) attention (fp16 mma, writes half2-packed ctx)
    attn_h<<<dim3(NHEAD, T_LEN / 64), 128, ATT_SMEM_BYTES>>>(qp, kvp, ctxh);
    // 4) out = ctx @ Wo + bo
    gemm_h<<<dim3(D_DIM / 128, T_LEN / 128), 256, GSMEM_BYTES>>>(
        ctxh, woh, out, bo, D_DIM, D_DIM / 128, woh, out, D_DIM);

    (void)in_sizes; (void)n_in; (void)out_size;
}

// round 15
// speedup vs baseline: 2.0517x; 1.1045x over previous
#include <cuda_runtime.h>
#include <cuda_fp16.h>
#include <cuda_bf16.h>
#include <cstdint>
#include <math.h>

// Problem constants
#define T_LEN 2048
#define D_DIM 4096
#define NHEAD 32
#define NGRP 8
#define HDIM 128
#define KVDIM 2048   // 2 * HDIM * NGRP

// Scratch (no cudaMalloc allowed)
__device__ uint32_t g_qh2[T_LEN * D_DIM / 2];    // 16 MB q  packed [T][2048]
__device__ uint32_t g_kvh2[T_LEN * KVDIM / 2];   //  8 MB kv packed [T][1024]
__device__ uint32_t g_ctxh[T_LEN * D_DIM / 2];   // 16 MB ctx packed
__device__ uint32_t g_xh[T_LEN * D_DIM / 2];     // 16 MB x packed [T][2048]
__device__ uint32_t g_wqh[D_DIM / 2 * D_DIM];    // 32 MB Wq  [K/2][N]
__device__ uint32_t g_wkvh[D_DIM / 2 * KVDIM];   // 16 MB Wkv [K/2][N]
__device__ uint32_t g_woh[D_DIM / 2 * D_DIM];    // 32 MB Wo  [K/2][N]

// ---------------------------------------------------------------------------
// Helpers
// ---------------------------------------------------------------------------
__device__ __forceinline__ uint32_t smem_u32(const void* p) {
    uint32_t a;
    asm("{ .reg .u64 t; cvta.to.shared.u64 t, %1; cvt.u32.u64 %0, t; }"
        : "=r"(a) : "l"(p));
    return a;
}
#define CP_ASYNC16(smem, gptr) \
    asm volatile("cp.async.cg.shared.global [%0], [%1], 16;" \
                 :: "r"(smem), "l"(gptr) : "memory")
#define CP_COMMIT() asm volatile("cp.async.commit_group;" ::: "memory")
#define CP_WAIT(N)  asm volatile("cp.async.wait_group %0;" :: "n"(N) : "memory")
#define LDSM_X4(r0, r1, r2, r3, addr) \
    asm volatile("ldmatrix.sync.aligned.m8n8.x4.shared.b16 {%0,%1,%2,%3}, [%4];" \
                 : "=r"(r0), "=r"(r1), "=r"(r2), "=r"(r3) : "r"(addr))

__device__ __forceinline__ uint32_t packh2(float a, float b) {
    __half2 h = __floats2half2_rn(a, b);
    return *reinterpret_cast<uint32_t*>(&h);
}
__device__ __forceinline__ uint32_t h2_lows(uint32_t a, uint32_t b) {
    __half2 r = __lows2half2(*(__half2*)&a, *(__half2*)&b);
    return *reinterpret_cast<uint32_t*>(&r);
}
__device__ __forceinline__ uint32_t h2_highs(uint32_t a, uint32_t b) {
    __half2 r = __highs2half2(*(__half2*)&a, *(__half2*)&b);
    return *reinterpret_cast<uint32_t*>(&r);
}
__device__ __forceinline__ void mma_f16(float* c, const uint32_t* a,
                                        const uint32_t* b) {
    asm volatile(
        "mma.sync.aligned.m16n8k16.row.col.f32.f16.f16.f32 "
        "{%0,%1,%2,%3}, {%4,%5,%6,%7}, {%8,%9}, {%0,%1,%2,%3};"
        : "+f"(c[0]), "+f"(c[1]), "+f"(c[2]), "+f"(c[3])
        : "r"(a[0]), "r"(a[1]), "r"(a[2]), "r"(a[3]), "r"(b[0]), "r"(b[1]));
}

// ---------------------------------------------------------------------------
// Merged prepass: pack x, Wq, Wkv, Wo into fp16 in ONE launch.
// x:  out[i] = h2(x[2i], x[2i+1])
// W:  out[kp*N+n] = h2(W[2kp*N+n], W[(2kp+1)*N+n])
// ---------------------------------------------------------------------------
#define SX  (T_LEN * D_DIM / 2)            // 4M
#define SQW (D_DIM / 2 * D_DIM)            // 8M
#define SKW (D_DIM / 2 * KVDIM)            // 4M
#define SOW (D_DIM / 2 * D_DIM)            // 8M
#define STOT (SX + SQW + SKW + SOW)        // 24M

__global__ __launch_bounds__(256) void pack_all(
    const float* __restrict__ x,  const float* __restrict__ Wq,
    const float* __restrict__ Wkv, const float* __restrict__ Wo,
    uint32_t* __restrict__ xh, uint32_t* __restrict__ wqh,
    uint32_t* __restrict__ wkvh, uint32_t* __restrict__ woh)
{
    long long i = (long long)blockIdx.x * 256 + threadIdx.x;
    if (i < SX) {
        const float2 v = ((const float2*)x)[i];
        xh[i] = packh2(v.x, v.y);
    } else if (i < SX + SQW) {
        long long j = i - SX;
        int kp = (int)(j >> 12), n = (int)(j & 4095);
        wqh[j] = packh2(Wq[(size_t)(2 * kp) * D_DIM + n],
                        Wq[(size_t)(2 * kp + 1) * D_DIM + n]);
    } else if (i < SX + SQW + SKW) {
        long long j = i - SX - SQW;
        int kp = (int)(j >> 11), n = (int)(j & 2047);
        wkvh[j] = packh2(Wkv[(size_t)(2 * kp) * KVDIM + n],
                         Wkv[(size_t)(2 * kp + 1) * KVDIM + n]);
    } else if (i < STOT) {
        long long j = i - SX - SQW - SKW;
        int kp = (int)(j >> 12), n = (int)(j & 4095);
        woh[j] = packh2(Wo[(size_t)(2 * kp) * D_DIM + n],
                        Wo[(size_t)(2 * kp + 1) * D_DIM + n]);
    }
}

// ---------------------------------------------------------------------------
// fp16 mma.sync GEMM (m16n8k16), A-fragments via ldmatrix.x4 (R14-proven).
// Epilogue: pack0/pack1 select fp16-packed u32 output vs f32(+bias).
// ---------------------------------------------------------------------------
#define GK2 2048
#define NT 128
#define AS_STRIDE 20
#define BS_STRIDE 136
#define AS_U (128 * AS_STRIDE)
#define BS_U (16 * BS_STRIDE)
#define STAGE_U (AS_U + BS_U)
#define NSTAGE 3
#define GSMEM_BYTES (NSTAGE * STAGE_U * 4)

__global__ __launch_bounds__(256, 2) void gemm_h(
    const uint32_t* __restrict__ A,
    const uint32_t* __restrict__ B0, void* __restrict__ C0,
    const float* __restrict__ bias0, int N0, int NX0, int pack0,
    const uint32_t* __restrict__ B1, void* __restrict__ C1, int N1, int pack1)
{
    extern __shared__ uint32_t sh[];
    const uint32_t smb = smem_u32(sh);

    const int tid = threadIdx.x;
    const int wid = tid >> 5;
    const int lane = tid & 31;
    const int gid = lane >> 2;
    const int tig = lane & 3;
    const int warp_m = (wid & 1) * 64;
    const int warp_n = (wid >> 1) * 32;

    const int by = blockIdx.y;
    int bx = blockIdx.x;

    const uint32_t* B; void* C; const float* bias; int N, pack;
    if (bx < NX0) { B = B0; C = C0; bias = bias0; N = N0; pack = pack0; }
    else { B = B1; C = C1; bias = nullptr; N = N1; pack = pack1; bx -= NX0; }

    const uint32_t* Ab = A + (size_t)by * 128 * GK2;
    const uint32_t* Bb = B + (size_t)bx * 128;

    auto load_tile = [&](int kt, int s) {
        const uint32_t* ag = Ab + kt * 16;
        const uint32_t* bg = Bb + (size_t)(kt * 16) * N;
        uint32_t ab = smb + 4 * (s * STAGE_U);
        uint32_t bb = ab + 4 * AS_U;
#pragma unroll
        for (int i = 0; i < 2; i++) {
            int id = tid + i * 256;
            int r = id >> 2, c = (id & 3) * 4;
            CP_ASYNC16(ab + (r * AS_STRIDE + c) * 4, ag + (size_t)r * GK2 + c);
        }
#pragma unroll
        for (int i = 0; i < 2; i++) {
            int id = tid + i * 256;
            int r = id >> 5, c = (id & 31) * 4;
            CP_ASYNC16(bb + (r * BS_STRIDE + c) * 4, bg + (size_t)r * N + c);
        }
        CP_COMMIT();
    };

    const int lmr = lane & 15;
    const int lmc = (lane >> 4) * 4;

    float acc[4][4][4];
#pragma unroll
    for (int i = 0; i < 4; i++)
#pragma unroll
        for (int j = 0; j < 4; j++)
#pragma unroll
            for (int k = 0; k < 4; k++) acc[i][j][k] = 0.f;

    load_tile(0, 0);
    load_tile(1, 1);

    for (int kt = 0; kt < NT; kt++) {
        if (kt < NT - 1) { CP_WAIT(1); } else { CP_WAIT(0); }
        __syncthreads();
        if (kt + 2 < NT) load_tile(kt + 2, (kt + 2) % NSTAGE);

        const uint32_t sbase = smb + 4 * ((kt % NSTAGE) * STAGE_U);
        const uint32_t* bs = sh + (kt % NSTAGE) * STAGE_U + AS_U;

#pragma unroll
        for (int ks = 0; ks < 2; ks++) {
            const int k0 = ks * 8;
            uint32_t afr[4][4];
#pragma unroll
            for (int mf = 0; mf < 4; mf++) {
                uint32_t ad = sbase +
                    4 * ((warp_m + mf * 16 + lmr) * AS_STRIDE + k0 + lmc);
                LDSM_X4(afr[mf][0], afr[mf][1], afr[mf][2], afr[mf][3], ad);
            }
            uint32_t bfr[4][2];
#pragma unroll
            for (int nf = 0; nf < 4; nf++) {
                const uint32_t* bp = bs + (k0 + tig) * BS_STRIDE + warp_n + nf * 8 + gid;
                bfr[nf][0] = bp[0];
                bfr[nf][1] = bp[4 * BS_STRIDE];
            }
#pragma unroll
            for (int mf = 0; mf < 4; mf++)
#pragma unroll
                for (int nf = 0; nf < 4; nf++)
                    mma_f16(acc[mf][nf], afr[mf], bfr[nf]);
        }
    }

    // Epilogue
#pragma unroll
    for (int mf = 0; mf < 4; mf++) {
#pragma unroll
        for (int nf = 0; nf < 4; nf++) {
            int row0 = by * 128 + warp_m + mf * 16 + gid;
            int col  = bx * 128 + warp_n + nf * 8 + tig * 2;
            if (pack) {
                uint32_t* Cp = (uint32_t*)C;
                Cp[(size_t)row0 * (N / 2) + col / 2] =
                    packh2(acc[mf][nf][0], acc[mf][nf][1]);
                Cp[(size_t)(row0 + 8) * (N / 2) + col / 2] =
                    packh2(acc[mf][nf][2], acc[mf][nf][3]);
            } else {
                float* Cf = (float*)C;
                float b0 = 0.f, b1 = 0.f;
                if (bias) { b0 = __ldg(bias + col); b1 = __ldg(bias + col + 1); }
                *(float2*)(Cf + (size_t)row0 * N + col) =
                    make_float2(acc[mf][nf][0] + b0, acc[mf][nf][1] + b1);
                *(float2*)(Cf + (size_t)(row0 + 8) * N + col) =
                    make_float2(acc[mf][nf][2] + b0, acc[mf][nf][3] + b1);
            }
        }
    }
}

// ---------------------------------------------------------------------------
// fp16 tensor-core causal GQA flash attention.
// Inputs q/kv are fp16-packed u32.  K tile via cp.async (pure copy);
// V tile repacked across key pairs with half2 lows/highs mixes.
// ---------------------------------------------------------------------------
#define KSTR 68
#define VSTR 136
#define PSTR 36
#define ATT_SMEM_UINTS (64 * KSTR + 32 * VSTR + 4 * 16 * PSTR)
#define ATT_SMEM_BYTES (ATT_SMEM_UINTS * 4)
#define QROW (D_DIM / 2)     // 2048 u32 per q row
#define KVROW (KVDIM / 2)    // 1024 u32 per kv row

__global__ __launch_bounds__(128, 2) void attn_h(
    const uint32_t* __restrict__ qh2, const uint32_t* __restrict__ kvh2,
    uint32_t* __restrict__ ctxh)
{
    const int h  = blockIdx.x;
    const int qt = blockIdx.y;
    const int g  = h >> 2;

    extern __shared__ uint32_t smu[];
    uint32_t* Ksh = smu;
    uint32_t* Vsh = Ksh + 64 * KSTR;
    uint32_t* Psh = Vsh + 32 * VSTR;
    const uint32_t ksh_base = smem_u32(Ksh);

    const int tid  = threadIdx.x;
    const int wid  = tid >> 5;
    const int lane = tid & 31;
    const int gid  = lane >> 2;
    const int tig  = lane & 3;

    uint32_t* Pw = Psh + wid * 16 * PSTR;
    const uint32_t pw_base = smem_u32(Pw);
    const int lmr = lane & 15;
    const int lmc = (lane >> 4) * 4;

    const int r0 = qt * 64 + wid * 16;
    const int rowg0 = r0 + gid;
    const int rowg1 = r0 + gid + 8;

    // Q fragments: direct u32 loads from packed q
    uint32_t qf[8][4];
    {
        const uint32_t* qb = qh2 + (size_t)rowg0 * QROW + h * (HDIM / 2);
#pragma unroll
        for (int kf = 0; kf < 8; kf++) {
            qf[kf][0] = qb[kf * 8 + tig];
            qf[kf][1] = qb[8 * QROW + kf * 8 + tig];
            qf[kf][2] = qb[kf * 8 + tig + 4];
            qf[kf][3] = qb[8 * QROW + kf * 8 + tig + 4];
        }
    }

    float o[16][4];
#pragma unroll
    for (int nf = 0; nf < 16; nf++)
#pragma unroll
        for (int j = 0; j < 4; j++) o[nf][j] = 0.f;
    float m0 = -1e30f, m1 = -1e30f, l0 = 0.f, l1 = 0.f;
    const float scale = 0.08838834764831845f;

    for (int kt = 0; kt <= qt; kt++) {
        __syncthreads();   // prior tile's smem reads complete
        const uint32_t* kvb = kvh2 + (size_t)(kt * 64) * KVROW + g * 128;

        // K: pure copy via cp.async — 64 keys x 64 u32, 16B chunks (8/thread)
#pragma unroll
        for (int i = 0; i < 8; i++) {
            int id = tid + i * 128;
            int row = id >> 4, c4 = (id & 15) * 4;
            CP_ASYNC16(ksh_base + 4 * (row * KSTR + c4),
                       kvb + (size_t)row * KVROW + c4);
        }
        CP_COMMIT();

        // V: repack across key pairs — 32 kpr x 32 uint4 chunks (8/thread)
#pragma unroll
        for (int i = 0; i < 8; i++) {
            int id = tid + i * 128;
            int kpr = id >> 5, q4 = id & 31;
            int d0 = q4 * 4;
            const uint32_t* s0 = kvb + (size_t)(2 * kpr) * KVROW + 64 + d0 / 2;
            uint2 a = *(const uint2*)s0;
            uint2 b = *(const uint2*)(s0 + KVROW);
            uint4 outv;
            outv.x = h2_lows(a.x, b.x);
            outv.y = h2_highs(a.x, b.x);
            outv.z = h2_lows(a.y, b.y);
            outv.w = h2_highs(a.y, b.y);
            *(uint4*)(Vsh + kpr * VSTR + d0) = outv;
        }
        CP_WAIT(0);
        __syncthreads();

        // ---- S = Q @ K^T ----
        float sa[8][4];
#pragma unroll
        for (int nf = 0; nf < 8; nf++)
#pragma unroll
            for (int j = 0; j < 4; j++) sa[nf][j] = 0.f;

#pragma unroll
        for (int kf = 0; kf < 8; kf++) {
#pragma unroll
            for (int nf = 0; nf < 8; nf++) {
                const uint32_t* kp = Ksh + (nf * 8 + gid) * KSTR + kf * 8 + tig;
                uint32_t bfr[2] = { kp[0], kp[4] };
                mma_f16(sa[nf], qf[kf], bfr);
            }
        }

        // ---- scale + causal mask ----
        const bool diag = (kt == qt);
#pragma unroll
        for (int nf = 0; nf < 8; nf++) {
            int c = kt * 64 + nf * 8 + 2 * tig;
#pragma unroll
            for (int j = 0; j < 4; j++) sa[nf][j] *= scale;
            if (diag) {
                if (c     > rowg0) sa[nf][0] = -1e30f;
                if (c + 1 > rowg0) sa[nf][1] = -1e30f;
                if (c     > rowg1) sa[nf][2] = -1e30f;
                if (c + 1 > rowg1) sa[nf][3] = -1e30f;
            }
        }

        float mx0 = -1e30f, mx1 = -1e30f;
#pragma unroll
        for (int nf = 0; nf < 8; nf++) {
            mx0 = fmaxf(mx0, fmaxf(sa[nf][0], sa[nf][1]));
            mx1 = fmaxf(mx1, fmaxf(sa[nf][2], sa[nf][3]));
        }
        mx0 = fmaxf(mx0, __shfl_xor_sync(0xffffffff, mx0, 1));
        mx0 = fmaxf(mx0, __shfl_xor_sync(0xffffffff, mx0, 2));
        mx1 = fmaxf(mx1, __shfl_xor_sync(0xffffffff, mx1, 1));
        mx1 = fmaxf(mx1, __shfl_xor_sync(0xffffffff, mx1, 2));

        float mn0 = fmaxf(m0, mx0), mn1 = fmaxf(m1, mx1);
        float al0 = __expf(m0 - mn0), al1 = __expf(m1 - mn1);

        float s0 = 0.f, s1 = 0.f;
#pragma unroll
        for (int nf = 0; nf < 8; nf++) {
            float p00 = __expf(sa[nf][0] - mn0);
            float p01 = __expf(sa[nf][1] - mn0);
            float p10 = __expf(sa[nf][2] - mn1);
            float p11 = __expf(sa[nf][3] - mn1);
            s0 += p00 + p01;
            s1 += p10 + p11;
            int kp = nf * 4 + tig;
            Pw[gid * PSTR + kp]       = packh2(p00, p01);
            Pw[(gid + 8) * PSTR + kp] = packh2(p10, p11);
        }
        s0 += __shfl_xor_sync(0xffffffff, s0, 1);
        s0 += __shfl_xor_sync(0xffffffff, s0, 2);
        s1 += __shfl_xor_sync(0xffffffff, s1, 1);
        s1 += __shfl_xor_sync(0xffffffff, s1, 2);

        l0 = l0 * al0 + s0;
        l1 = l1 * al1 + s1;
        m0 = mn0; m1 = mn1;

#pragma unroll
        for (int nf = 0; nf < 16; nf++) {
            o[nf][0] *= al0; o[nf][1] *= al0;
            o[nf][2] *= al1; o[nf][3] *= al1;
        }
        __syncwarp();

        // ---- O += P @ V ----
#pragma unroll
        for (int kf = 0; kf < 4; kf++) {
            uint32_t pa[4];
            uint32_t pad = pw_base + 4 * (lmr * PSTR + kf * 8 + lmc);
            LDSM_X4(pa[0], pa[1], pa[2], pa[3], pad);
#pragma unroll
            for (int nf = 0; nf < 16; nf++) {
                const uint32_t* vp = Vsh + (kf * 8 + tig) * VSTR + nf * 8 + gid;
                uint32_t bfr[2] = { vp[0], vp[4 * VSTR] };
                mma_f16(o[nf], pa, bfr);
            }
        }
        __syncwarp();
    }

    float inv0 = 1.0f / l0, inv1 = 1.0f / l1;
    uint32_t* cb = ctxh + (size_t)rowg0 * QROW + h * (HDIM / 2);
#pragma unroll
    for (int nf = 0; nf < 16; nf++) {
        int cp = nf * 4 + tig;
        cb[cp] = packh2(o[nf][0] * inv0, o[nf][1] * inv0);
        cb[8 * QROW + cp] = packh2(o[nf][2] * inv1, o[nf][3] * inv1);
    }
}

// ---------------------------------------------------------------------------
// Launch
// ---------------------------------------------------------------------------
extern "C" void kernel_launch(void* const* d_in, const int* in_sizes, int n_in,
                              void* d_out, int out_size)
{
    const float* x   = (const float*)d_in[0];
    const float* Wq  = (const float*)d_in[1];
    const float* Wkv = (const float*)d_in[2];
    const float* Wo  = (const float*)d_in[3];
    const float* bo  = (const float*)d_in[4];
    float* out = (float*)d_out;

    uint32_t *qh2, *kvh2, *ctxh, *xh, *wqh, *wkvh, *woh;
    cudaGetSymbolAddress((void**)&qh2,  g_qh2);
    cudaGetSymbolAddress((void**)&kvh2, g_kvh2);
    cudaGetSymbolAddress((void**)&ctxh, g_ctxh);
    cudaGetSymbolAddress((void**)&xh,   g_xh);
    cudaGetSymbolAddress((void**)&wqh,  g_wqh);
    cudaGetSymbolAddress((void**)&wkvh, g_wkvh);
    cudaGetSymbolAddress((void**)&woh,  g_woh);

    cudaFuncSetAttribute(attn_h,
                         cudaFuncAttributeMaxDynamicSharedMemorySize,
                         ATT_SMEM_BYTES);
    cudaFuncSetAttribute(gemm_h,
                         cudaFuncAttributeMaxDynamicSharedMemorySize,
                         GSMEM_BYTES);

    // Prepass: pack everything in one launch
    pack_all<<<(STOT + 255) / 256, 256>>>(x, Wq, Wkv, Wo, xh, wqh, wkvh, woh);

    // 1+2) fused: q = x@Wq (bx<32, packed), kv = x@Wkv (bx>=32, packed)
    gemm_h<<<dim3(D_DIM / 128 + KVDIM / 128, T_LEN / 128), 256, GSMEM_BYTES>>>(
        xh, wqh, qh2, nullptr, D_DIM, D_DIM / 128, 1, wkvh, kvh2, KVDIM, 1);
    // 3) attention (fp16 in/out)
    attn_h<<<dim3(NHEAD, T_LEN / 64), 128, ATT_SMEM_BYTES>>>(qh2, kvh2, ctxh);
    // 4) out = ctx @ Wo + bo (f32 output)
    gemm_h<<<dim3(D_DIM / 128, T_LEN / 128), 256, GSMEM_BYTES>>>(
        ctxh, woh, out, bo, D_DIM, D_DIM / 128, 0, woh, out, D_DIM, 0);

    (void)in_sizes; (void)n_in; (void)out_size;
}

// round 16
// speedup vs baseline: 2.0615x; 1.0047x over previous
#include <cuda_runtime.h>
#include <cuda_fp16.h>
#include <cuda_bf16.h>
#include <cstdint>
#include <math.h>

// Problem constants
#define T_LEN 2048
#define D_DIM 4096
#define NHEAD 32
#define NGRP 8
#define HDIM 128
#define KVDIM 2048   // 2 * HDIM * NGRP

// Scratch (no cudaMalloc allowed)
__device__ uint32_t g_qh2[T_LEN * D_DIM / 2];    // 16 MB q  packed [T][2048]
__device__ uint32_t g_kvh2[T_LEN * KVDIM / 2];   //  8 MB kv packed [T][1024]
__device__ uint32_t g_ctxh[T_LEN * D_DIM / 2];   // 16 MB ctx packed
__device__ uint32_t g_xh[T_LEN * D_DIM / 2];     // 16 MB x packed [T][2048]
__device__ uint32_t g_wqh[D_DIM / 2 * D_DIM];    // 32 MB Wq  [K/2][N]
__device__ uint32_t g_wkvh[D_DIM / 2 * KVDIM];   // 16 MB Wkv [K/2][N]
__device__ uint32_t g_woh[D_DIM / 2 * D_DIM];    // 32 MB Wo  [K/2][N]

// ---------------------------------------------------------------------------
// Helpers
// ---------------------------------------------------------------------------
__device__ __forceinline__ uint32_t smem_u32(const void* p) {
    uint32_t a;
    asm("{ .reg .u64 t; cvta.to.shared.u64 t, %1; cvt.u32.u64 %0, t; }"
        : "=r"(a) : "l"(p));
    return a;
}
#define CP_ASYNC16(smem, gptr) \
    asm volatile("cp.async.cg.shared.global [%0], [%1], 16;" \
                 :: "r"(smem), "l"(gptr) : "memory")
#define CP_COMMIT() asm volatile("cp.async.commit_group;" ::: "memory")
#define CP_WAIT(N)  asm volatile("cp.async.wait_group %0;" :: "n"(N) : "memory")
#define LDSM_X4(r0, r1, r2, r3, addr) \
    asm volatile("ldmatrix.sync.aligned.m8n8.x4.shared.b16 {%0,%1,%2,%3}, [%4];" \
                 : "=r"(r0), "=r"(r1), "=r"(r2), "=r"(r3) : "r"(addr))

__device__ __forceinline__ uint32_t packh2(float a, float b) {
    __half2 h = __floats2half2_rn(a, b);
    return *reinterpret_cast<uint32_t*>(&h);
}
__device__ __forceinline__ uint32_t h2_lows(uint32_t a, uint32_t b) {
    __half2 r = __lows2half2(*(__half2*)&a, *(__half2*)&b);
    return *reinterpret_cast<uint32_t*>(&r);
}
__device__ __forceinline__ uint32_t h2_highs(uint32_t a, uint32_t b) {
    __half2 r = __highs2half2(*(__half2*)&a, *(__half2*)&b);
    return *reinterpret_cast<uint32_t*>(&r);
}
__device__ __forceinline__ void mma_f16(float* c, const uint32_t* a,
                                        const uint32_t* b) {
    asm volatile(
        "mma.sync.aligned.m16n8k16.row.col.f32.f16.f16.f32 "
        "{%0,%1,%2,%3}, {%4,%5,%6,%7}, {%8,%9}, {%0,%1,%2,%3};"
        : "+f"(c[0]), "+f"(c[1]), "+f"(c[2]), "+f"(c[3])
        : "r"(a[0]), "r"(a[1]), "r"(a[2]), "r"(a[3]), "r"(b[0]), "r"(b[1]));
}

// ---------------------------------------------------------------------------
// Merged prepass (R15-proven): pack x, Wq, Wkv, Wo into fp16 in ONE launch.
// ---------------------------------------------------------------------------
#define SX  (T_LEN * D_DIM / 2)
#define SQW (D_DIM / 2 * D_DIM)
#define SKW (D_DIM / 2 * KVDIM)
#define SOW (D_DIM / 2 * D_DIM)
#define STOT (SX + SQW + SKW + SOW)

__global__ __launch_bounds__(256) void pack_all(
    const float* __restrict__ x,  const float* __restrict__ Wq,
    const float* __restrict__ Wkv, const float* __restrict__ Wo,
    uint32_t* __restrict__ xh, uint32_t* __restrict__ wqh,
    uint32_t* __restrict__ wkvh, uint32_t* __restrict__ woh)
{
    long long i = (long long)blockIdx.x * 256 + threadIdx.x;
    if (i < SX) {
        const float2 v = ((const float2*)x)[i];
        xh[i] = packh2(v.x, v.y);
    } else if (i < SX + SQW) {
        long long j = i - SX;
        int kp = (int)(j >> 12), n = (int)(j & 4095);
        wqh[j] = packh2(Wq[(size_t)(2 * kp) * D_DIM + n],
                        Wq[(size_t)(2 * kp + 1) * D_DIM + n]);
    } else if (i < SX + SQW + SKW) {
        long long j = i - SX - SQW;
        int kp = (int)(j >> 11), n = (int)(j & 2047);
        wkvh[j] = packh2(Wkv[(size_t)(2 * kp) * KVDIM + n],
                         Wkv[(size_t)(2 * kp + 1) * KVDIM + n]);
    } else if (i < STOT) {
        long long j = i - SX - SQW - SKW;
        int kp = (int)(j >> 12), n = (int)(j & 4095);
        woh[j] = packh2(Wo[(size_t)(2 * kp) * D_DIM + n],
                        Wo[(size_t)(2 * kp + 1) * D_DIM + n]);
    }
}

// ---------------------------------------------------------------------------
// fp16 mma.sync GEMM (m16n8k16), R15-proven, unchanged.
// ---------------------------------------------------------------------------
#define GK2 2048
#define NT 128
#define AS_STRIDE 20
#define BS_STRIDE 136
#define AS_U (128 * AS_STRIDE)
#define BS_U (16 * BS_STRIDE)
#define STAGE_U (AS_U + BS_U)
#define NSTAGE 3
#define GSMEM_BYTES (NSTAGE * STAGE_U * 4)

__global__ __launch_bounds__(256, 2) void gemm_h(
    const uint32_t* __restrict__ A,
    const uint32_t* __restrict__ B0, void* __restrict__ C0,
    const float* __restrict__ bias0, int N0, int NX0, int pack0,
    const uint32_t* __restrict__ B1, void* __restrict__ C1, int N1, int pack1)
{
    extern __shared__ uint32_t sh[];
    const uint32_t smb = smem_u32(sh);

    const int tid = threadIdx.x;
    const int wid = tid >> 5;
    const int lane = tid & 31;
    const int gid = lane >> 2;
    const int tig = lane & 3;
    const int warp_m = (wid & 1) * 64;
    const int warp_n = (wid >> 1) * 32;

    const int by = blockIdx.y;
    int bx = blockIdx.x;

    const uint32_t* B; void* C; const float* bias; int N, pack;
    if (bx < NX0) { B = B0; C = C0; bias = bias0; N = N0; pack = pack0; }
    else { B = B1; C = C1; bias = nullptr; N = N1; pack = pack1; bx -= NX0; }

    const uint32_t* Ab = A + (size_t)by * 128 * GK2;
    const uint32_t* Bb = B + (size_t)bx * 128;

    auto load_tile = [&](int kt, int s) {
        const uint32_t* ag = Ab + kt * 16;
        const uint32_t* bg = Bb + (size_t)(kt * 16) * N;
        uint32_t ab = smb + 4 * (s * STAGE_U);
        uint32_t bb = ab + 4 * AS_U;
#pragma unroll
        for (int i = 0; i < 2; i++) {
            int id = tid + i * 256;
            int r = id >> 2, c = (id & 3) * 4;
            CP_ASYNC16(ab + (r * AS_STRIDE + c) * 4, ag + (size_t)r * GK2 + c);
        }
#pragma unroll
        for (int i = 0; i < 2; i++) {
            int id = tid + i * 256;
            int r = id >> 5, c = (id & 31) * 4;
            CP_ASYNC16(bb + (r * BS_STRIDE + c) * 4, bg + (size_t)r * N + c);
        }
        CP_COMMIT();
    };

    const int lmr = lane & 15;
    const int lmc = (lane >> 4) * 4;

    float acc[4][4][4];
#pragma unroll
    for (int i = 0; i < 4; i++)
#pragma unroll
        for (int j = 0; j < 4; j++)
#pragma unroll
            for (int k = 0; k < 4; k++) acc[i][j][k] = 0.f;

    load_tile(0, 0);
    load_tile(1, 1);

    for (int kt = 0; kt < NT; kt++) {
        if (kt < NT - 1) { CP_WAIT(1); } else { CP_WAIT(0); }
        __syncthreads();
        if (kt + 2 < NT) load_tile(kt + 2, (kt + 2) % NSTAGE);

        const uint32_t sbase = smb + 4 * ((kt % NSTAGE) * STAGE_U);
        const uint32_t* bs = sh + (kt % NSTAGE) * STAGE_U + AS_U;

#pragma unroll
        for (int ks = 0; ks < 2; ks++) {
            const int k0 = ks * 8;
            uint32_t afr[4][4];
#pragma unroll
            for (int mf = 0; mf < 4; mf++) {
                uint32_t ad = sbase +
                    4 * ((warp_m + mf * 16 + lmr) * AS_STRIDE + k0 + lmc);
                LDSM_X4(afr[mf][0], afr[mf][1], afr[mf][2], afr[mf][3], ad);
            }
            uint32_t bfr[4][2];
#pragma unroll
            for (int nf = 0; nf < 4; nf++) {
                const uint32_t* bp = bs + (k0 + tig) * BS_STRIDE + warp_n + nf * 8 + gid;
                bfr[nf][0] = bp[0];
                bfr[nf][1] = bp[4 * BS_STRIDE];
            }
#pragma unroll
            for (int mf = 0; mf < 4; mf++)
#pragma unroll
                for (int nf = 0; nf < 4; nf++)
                    mma_f16(acc[mf][nf], afr[mf], bfr[nf]);
        }
    }

#pragma unroll
    for (int mf = 0; mf < 4; mf++) {
#pragma unroll
        for (int nf = 0; nf < 4; nf++) {
            int row0 = by * 128 + warp_m + mf * 16 + gid;
            int col  = bx * 128 + warp_n + nf * 8 + tig * 2;
            if (pack) {
                uint32_t* Cp = (uint32_t*)C;
                Cp[(size_t)row0 * (N / 2) + col / 2] =
                    packh2(acc[mf][nf][0], acc[mf][nf][1]);
                Cp[(size_t)(row0 + 8) * (N / 2) + col / 2] =
                    packh2(acc[mf][nf][2], acc[mf][nf][3]);
            } else {
                float* Cf = (float*)C;
                float b0 = 0.f, b1 = 0.f;
                if (bias) { b0 = __ldg(bias + col); b1 = __ldg(bias + col + 1); }
                *(float2*)(Cf + (size_t)row0 * N + col) =
                    make_float2(acc[mf][nf][0] + b0, acc[mf][nf][1] + b1);
                *(float2*)(Cf + (size_t)(row0 + 8) * N + col) =
                    make_float2(acc[mf][nf][2] + b0, acc[mf][nf][3] + b1);
            }
        }
    }
}

// ---------------------------------------------------------------------------
// fp16 causal GQA flash attention — 128-row query tiles, 8 warps/block.
// Grid (NHEAD, T/128), heavy-first qt order.  K/V loaded once per 128 queries.
// ---------------------------------------------------------------------------
#define KSTR 68
#define VSTR 136
#define PSTR 36
#define ATT_SMEM_UINTS (64 * KSTR + 32 * VSTR + 8 * 16 * PSTR)   // 13312
#define ATT_SMEM_BYTES (ATT_SMEM_UINTS * 4)                      // 53248
#define QROW (D_DIM / 2)
#define KVROW (KVDIM / 2)

__global__ __launch_bounds__(256, 2) void attn_h(
    const uint32_t* __restrict__ qh2, const uint32_t* __restrict__ kvh2,
    uint32_t* __restrict__ ctxh)
{
    const int h  = blockIdx.x;
    const int qt = (T_LEN / 128 - 1) - blockIdx.y;   // heavy-first
    const int g  = h >> 2;

    extern __shared__ uint32_t smu[];
    uint32_t* Ksh = smu;
    uint32_t* Vsh = Ksh + 64 * KSTR;
    uint32_t* Psh = Vsh + 32 * VSTR;
    const uint32_t ksh_base = smem_u32(Ksh);

    const int tid  = threadIdx.x;
    const int wid  = tid >> 5;
    const int lane = tid & 31;
    const int gid  = lane >> 2;
    const int tig  = lane & 3;

    uint32_t* Pw = Psh + wid * 16 * PSTR;
    const uint32_t pw_base = smem_u32(Pw);
    const int lmr = lane & 15;
    const int lmc = (lane >> 4) * 4;

    const int r0 = qt * 128 + wid * 16;
    const int rowg0 = r0 + gid;
    const int rowg1 = r0 + gid + 8;

    // Q fragments: direct u32 loads from packed q
    uint32_t qf[8][4];
    {
        const uint32_t* qb = qh2 + (size_t)rowg0 * QROW + h * (HDIM / 2);
#pragma unroll
        for (int kf = 0; kf < 8; kf++) {
            qf[kf][0] = qb[kf * 8 + tig];
            qf[kf][1] = qb[8 * QROW + kf * 8 + tig];
            qf[kf][2] = qb[kf * 8 + tig + 4];
            qf[kf][3] = qb[8 * QROW + kf * 8 + tig + 4];
        }
    }

    float o[16][4];
#pragma unroll
    for (int nf = 0; nf < 16; nf++)
#pragma unroll
        for (int j = 0; j < 4; j++) o[nf][j] = 0.f;
    float m0 = -1e30f, m1 = -1e30f, l0 = 0.f, l1 = 0.f;
    const float scale = 0.08838834764831845f;

    const int ktmax = 2 * qt + 1;
    for (int kt = 0; kt <= ktmax; kt++) {
        __syncthreads();
        const uint32_t* kvb = kvh2 + (size_t)(kt * 64) * KVROW + g * 128;

        // K: pure copy via cp.async — 1024 16B chunks, 4/thread
#pragma unroll
        for (int i = 0; i < 4; i++) {
            int id = tid + i * 256;
            int row = id >> 4, c4 = (id & 15) * 4;
            CP_ASYNC16(ksh_base + 4 * (row * KSTR + c4),
                       kvb + (size_t)row * KVROW + c4);
        }
        CP_COMMIT();

        // V: repack across key pairs — 1024 uint4 chunks, 4/thread
#pragma unroll
        for (int i = 0; i < 4; i++) {
            int id = tid + i * 256;
            int kpr = id >> 5, q4 = id & 31;
            int d0 = q4 * 4;
            const uint32_t* s0 = kvb + (size_t)(2 * kpr) * KVROW + 64 + d0 / 2;
            uint2 a = *(const uint2*)s0;
            uint2 b = *(const uint2*)(s0 + KVROW);
            uint4 outv;
            outv.x = h2_lows(a.x, b.x);
            outv.y = h2_highs(a.x, b.x);
            outv.z = h2_lows(a.y, b.y);
            outv.w = h2_highs(a.y, b.y);
            *(uint4*)(Vsh + kpr * VSTR + d0) = outv;
        }
        CP_WAIT(0);
        __syncthreads();

        // ---- S = Q @ K^T ----
        float sa[8][4];
#pragma unroll
        for (int nf = 0; nf < 8; nf++)
#pragma unroll
            for (int j = 0; j < 4; j++) sa[nf][j] = 0.f;

#pragma unroll
        for (int kf = 0; kf < 8; kf++) {
#pragma unroll
            for (int nf = 0; nf < 8; nf++) {
                const uint32_t* kp = Ksh + (nf * 8 + gid) * KSTR + kf * 8 + tig;
                uint32_t bfr[2] = { kp[0], kp[4] };
                mma_f16(sa[nf], qf[kf], bfr);
            }
        }

        // ---- scale + causal mask (per-warp diag condition) ----
        const bool diag = (kt * 64 + 63 > rowg0);
#pragma unroll
        for (int nf = 0; nf < 8; nf++) {
            int c = kt * 64 + nf * 8 + 2 * tig;
#pragma unroll
            for (int j = 0; j < 4; j++) sa[nf][j] *= scale;
            if (diag) {
                if (c     > rowg0) sa[nf][0] = -1e30f;
                if (c + 1 > rowg0) sa[nf][1] = -1e30f;
                if (c     > rowg1) sa[nf][2] = -1e30f;
                if (c + 1 > rowg1) sa[nf][3] = -1e30f;
            }
        }

        float mx0 = -1e30f, mx1 = -1e30f;
#pragma unroll
        for (int nf = 0; nf < 8; nf++) {
            mx0 = fmaxf(mx0, fmaxf(sa[nf][0], sa[nf][1]));
            mx1 = fmaxf(mx1, fmaxf(sa[nf][2], sa[nf][3]));
        }
        mx0 = fmaxf(mx0, __shfl_xor_sync(0xffffffff, mx0, 1));
        mx0 = fmaxf(mx0, __shfl_xor_sync(0xffffffff, mx0, 2));
        mx1 = fmaxf(mx1, __shfl_xor_sync(0xffffffff, mx1, 1));
        mx1 = fmaxf(mx1, __shfl_xor_sync(0xffffffff, mx1, 2));

        float mn0 = fmaxf(m0, mx0), mn1 = fmaxf(m1, mx1);
        float al0 = __expf(m0 - mn0), al1 = __expf(m1 - mn1);

        float s0 = 0.f, s1 = 0.f;
#pragma unroll
        for (int nf = 0; nf < 8; nf++) {
            float p00 = __expf(sa[nf][0] - mn0);
            float p01 = __expf(sa[nf][1] - mn0);
            float p10 = __expf(sa[nf][2] - mn1);
            float p11 = __expf(sa[nf][3] - mn1);
            s0 += p00 + p01;
            s1 += p10 + p11;
            int kp = nf * 4 + tig;
            Pw[gid * PSTR + kp]       = packh2(p00, p01);
            Pw[(gid + 8) * PSTR + kp] = packh2(p10, p11);
        }
        s0 += __shfl_xor_sync(0xffffffff, s0, 1);
        s0 += __shfl_xor_sync(0xffffffff, s0, 2);
        s1 += __shfl_xor_sync(0xffffffff, s1, 1);
        s1 += __shfl_xor_sync(0xffffffff, s1, 2);

        l0 = l0 * al0 + s0;
        l1 = l1 * al1 + s1;
        m0 = mn0; m1 = mn1;

#pragma unroll
        for (int nf = 0; nf < 16; nf++) {
            o[nf][0] *= al0; o[nf][1] *= al0;
            o[nf][2] *= al1; o[nf][3] *= al1;
        }
        __syncwarp();

        // ---- O += P @ V ----
#pragma unroll
        for (int kf = 0; kf < 4; kf++) {
            uint32_t pa[4];
            uint32_t pad = pw_base + 4 * (lmr * PSTR + kf * 8 + lmc);
            LDSM_X4(pa[0], pa[1], pa[2], pa[3], pad);
#pragma unroll
            for (int nf = 0; nf < 16; nf++) {
                const uint32_t* vp = Vsh + (kf * 8 + tig) * VSTR + nf * 8 + gid;
                uint32_t bfr[2] = { vp[0], vp[4 * VSTR] };
                mma_f16(o[nf], pa, bfr);
            }
        }
        __syncwarp();
    }

    float inv0 = 1.0f / l0, inv1 = 1.0f / l1;
    uint32_t* cb = ctxh + (size_t)rowg0 * QROW + h * (HDIM / 2);
#pragma unroll
    for (int nf = 0; nf < 16; nf++) {
        int cp = nf * 4 + tig;
        cb[cp] = packh2(o[nf][0] * inv0, o[nf][1] * inv0);
        cb[8 * QROW + cp] = packh2(o[nf][2] * inv1, o[nf][3] * inv1);
    }
}

// ---------------------------------------------------------------------------
// Launch
// ---------------------------------------------------------------------------
extern "C" void kernel_launch(void* const* d_in, const int* in_sizes, int n_in,
                              void* d_out, int out_size)
{
    const float* x   = (const float*)d_in[0];
    const float* Wq  = (const float*)d_in[1];
    const float* Wkv = (const float*)d_in[2];
    const float* Wo  = (const float*)d_in[3];
    const float* bo  = (const float*)d_in[4];
    float* out = (float*)d_out;

    uint32_t *qh2, *kvh2, *ctxh, *xh, *wqh, *wkvh, *woh;
    cudaGetSymbolAddress((void**)&qh2,  g_qh2);
    cudaGetSymbolAddress((void**)&kvh2, g_kvh2);
    cudaGetSymbolAddress((void**)&ctxh, g_ctxh);
    cudaGetSymbolAddress((void**)&xh,   g_xh);
    cudaGetSymbolAddress((void**)&wqh,  g_wqh);
    cudaGetSymbolAddress((void**)&wkvh, g_wkvh);
    cudaGetSymbolAddress((void**)&woh,  g_woh);

    cudaFuncSetAttribute(attn_h,
                         cudaFuncAttributeMaxDynamicSharedMemorySize,
                         ATT_SMEM_BYTES);
    cudaFuncSetAttribute(gemm_h,
                         cudaFuncAttributeMaxDynamicSharedMemorySize,
                         GSMEM_BYTES);

    // Prepass: pack everything in one launch
    pack_all<<<(STOT + 255) / 256, 256>>>(x, Wq, Wkv, Wo, xh, wqh, wkvh, woh);

    // 1+2) fused: q = x@Wq (bx<32, packed), kv = x@Wkv (bx>=32, packed)
    gemm_h<<<dim3(D_DIM / 128 + KVDIM / 128, T_LEN / 128), 256, GSMEM_BYTES>>>(
        xh, wqh, qh2, nullptr, D_DIM, D_DIM / 128, 1, wkvh, kvh2, KVDIM, 1);
    // 3) attention (fp16, 128-row q tiles, heavy-first)
    attn_h<<<dim3(NHEAD, T_LEN / 128), 256, ATT_SMEM_BYTES>>>(qh2, kvh2, ctxh);
    // 4) out = ctx @ Wo + bo (f32 output)
    gemm_h<<<dim3(D_DIM / 128, T_LEN / 128), 256, GSMEM_BYTES>>>(
        ctxh, woh, out, bo, D_DIM, D_DIM / 128, 0, woh, out, D_DIM, 0);

    (void)in_sizes; (void)n_in; (void)out_size;
}

// round 17
// speedup vs baseline: 2.1372x; 1.0367x over previous
#include <cuda_runtime.h>
#include <cuda_fp16.h>
#include <cuda_bf16.h>
#include <cstdint>
#include <math.h>

// Problem constants
#define T_LEN 2048
#define D_DIM 4096
#define NHEAD 32
#define NGRP 8
#define HDIM 128
#define KVDIM 2048   // 2 * HDIM * NGRP

// Scratch (no cudaMalloc allowed)
__device__ uint32_t g_qh2[T_LEN * D_DIM / 2];    // 16 MB q  packed [T][2048]
__device__ uint32_t g_kvh2[T_LEN * KVDIM / 2];   //  8 MB kv packed [T][1024]
__device__ uint32_t g_ctxh[T_LEN * D_DIM / 2];   // 16 MB ctx packed
__device__ uint32_t g_xh[T_LEN * D_DIM / 2];     // 16 MB x packed [T][2048]
__device__ uint32_t g_wqh[D_DIM / 2 * D_DIM];    // 32 MB Wq  [K/2][N]
__device__ uint32_t g_wkvh[D_DIM / 2 * KVDIM];   // 16 MB Wkv [K/2][N]
__device__ uint32_t g_woh[D_DIM / 2 * D_DIM];    // 32 MB Wo  [K/2][N]

// ---------------------------------------------------------------------------
// Helpers
// ---------------------------------------------------------------------------
__device__ __forceinline__ uint32_t smem_u32(const void* p) {
    uint32_t a;
    asm("{ .reg .u64 t; cvta.to.shared.u64 t, %1; cvt.u32.u64 %0, t; }"
        : "=r"(a) : "l"(p));
    return a;
}
#define CP_ASYNC16(smem, gptr) \
    asm volatile("cp.async.cg.shared.global [%0], [%1], 16;" \
                 :: "r"(smem), "l"(gptr) : "memory")
#define CP_COMMIT() asm volatile("cp.async.commit_group;" ::: "memory")
#define CP_WAIT(N)  asm volatile("cp.async.wait_group %0;" :: "n"(N) : "memory")
#define LDSM_X4(r0, r1, r2, r3, addr) \
    asm volatile("ldmatrix.sync.aligned.m8n8.x4.shared.b16 {%0,%1,%2,%3}, [%4];" \
                 : "=r"(r0), "=r"(r1), "=r"(r2), "=r"(r3) : "r"(addr))
#define LDSM_X4T(r0, r1, r2, r3, addr) \
    asm volatile("ldmatrix.sync.aligned.m8n8.x4.trans.shared.b16 {%0,%1,%2,%3}, [%4];" \
                 : "=r"(r0), "=r"(r1), "=r"(r2), "=r"(r3) : "r"(addr))

__device__ __forceinline__ uint32_t packh2(float a, float b) {
    __half2 h = __floats2half2_rn(a, b);
    return *reinterpret_cast<uint32_t*>(&h);
}
__device__ __forceinline__ void mma_f16(float* c, const uint32_t* a,
                                        const uint32_t* b) {
    asm volatile(
        "mma.sync.aligned.m16n8k16.row.col.f32.f16.f16.f32 "
        "{%0,%1,%2,%3}, {%4,%5,%6,%7}, {%8,%9}, {%0,%1,%2,%3};"
        : "+f"(c[0]), "+f"(c[1]), "+f"(c[2]), "+f"(c[3])
        : "r"(a[0]), "r"(a[1]), "r"(a[2]), "r"(a[3]), "r"(b[0]), "r"(b[1]));
}

// ---------------------------------------------------------------------------
// Merged, vectorized prepass: 4 packed u32 per thread.
// ---------------------------------------------------------------------------
#define SX  (T_LEN * D_DIM / 2)
#define SQW (D_DIM / 2 * D_DIM)
#define SKW (D_DIM / 2 * KVDIM)
#define SOW (D_DIM / 2 * D_DIM)
#define STOT (SX + SQW + SKW + SOW)

__global__ __launch_bounds__(256) void pack_all(
    const float* __restrict__ x,  const float* __restrict__ Wq,
    const float* __restrict__ Wkv, const float* __restrict__ Wo,
    uint32_t* __restrict__ xh, uint32_t* __restrict__ wqh,
    uint32_t* __restrict__ wkvh, uint32_t* __restrict__ woh)
{
    long long i4 = (long long)blockIdx.x * 256 + threadIdx.x;
    if (i4 < SX / 4) {
        float4 a = ((const float4*)x)[2 * i4];
        float4 b = ((const float4*)x)[2 * i4 + 1];
        uint4 o;
        o.x = packh2(a.x, a.y); o.y = packh2(a.z, a.w);
        o.z = packh2(b.x, b.y); o.w = packh2(b.z, b.w);
        ((uint4*)xh)[i4] = o;
    } else if (i4 < (SX + SQW) / 4) {
        long long j = i4 * 4 - SX;
        int kp = (int)(j >> 12), n = (int)(j & 4095);
        float4 r0 = *(const float4*)(Wq + (size_t)(2 * kp) * D_DIM + n);
        float4 r1 = *(const float4*)(Wq + (size_t)(2 * kp + 1) * D_DIM + n);
        uint4 o;
        o.x = packh2(r0.x, r1.x); o.y = packh2(r0.y, r1.y);
        o.z = packh2(r0.z, r1.z); o.w = packh2(r0.w, r1.w);
        *(uint4*)(wqh + j) = o;
    } else if (i4 < (SX + SQW + SKW) / 4) {
        long long j = i4 * 4 - SX - SQW;
        int kp = (int)(j >> 11), n = (int)(j & 2047);
        float4 r0 = *(const float4*)(Wkv + (size_t)(2 * kp) * KVDIM + n);
        float4 r1 = *(const float4*)(Wkv + (size_t)(2 * kp + 1) * KVDIM + n);
        uint4 o;
        o.x = packh2(r0.x, r1.x); o.y = packh2(r0.y, r1.y);
        o.z = packh2(r0.z, r1.z); o.w = packh2(r0.w, r1.w);
        *(uint4*)(wkvh + j) = o;
    } else if (i4 < STOT / 4) {
        long long j = i4 * 4 - SX - SQW - SKW;
        int kp = (int)(j >> 12), n = (int)(j & 4095);
        float4 r0 = *(const float4*)(Wo + (size_t)(2 * kp) * D_DIM + n);
        float4 r1 = *(const float4*)(Wo + (size_t)(2 * kp + 1) * D_DIM + n);
        uint4 o;
        o.x = packh2(r0.x, r1.x); o.y = packh2(r0.y, r1.y);
        o.z = packh2(r0.z, r1.z); o.w = packh2(r0.w, r1.w);
        *(uint4*)(woh + j) = o;
    }
}

// ---------------------------------------------------------------------------
// fp16 mma.sync GEMM (m16n8k16), R15-proven, unchanged.
// ---------------------------------------------------------------------------
#define GK2 2048
#define NT 128
#define AS_STRIDE 20
#define BS_STRIDE 136
#define AS_U (128 * AS_STRIDE)
#define BS_U (16 * BS_STRIDE)
#define STAGE_U (AS_U + BS_U)
#define NSTAGE 3
#define GSMEM_BYTES (NSTAGE * STAGE_U * 4)

__global__ __launch_bounds__(256, 2) void gemm_h(
    const uint32_t* __restrict__ A,
    const uint32_t* __restrict__ B0, void* __restrict__ C0,
    const float* __restrict__ bias0, int N0, int NX0, int pack0,
    const uint32_t* __restrict__ B1, void* __restrict__ C1, int N1, int pack1)
{
    extern __shared__ uint32_t sh[];
    const uint32_t smb = smem_u32(sh);

    const int tid = threadIdx.x;
    const int wid = tid >> 5;
    const int lane = tid & 31;
    const int gid = lane >> 2;
    const int tig = lane & 3;
    const int warp_m = (wid & 1) * 64;
    const int warp_n = (wid >> 1) * 32;

    const int by = blockIdx.y;
    int bx = blockIdx.x;

    const uint32_t* B; void* C; const float* bias; int N, pack;
    if (bx < NX0) { B = B0; C = C0; bias = bias0; N = N0; pack = pack0; }
    else { B = B1; C = C1; bias = nullptr; N = N1; pack = pack1; bx -= NX0; }

    const uint32_t* Ab = A + (size_t)by * 128 * GK2;
    const uint32_t* Bb = B + (size_t)bx * 128;

    auto load_tile = [&](int kt, int s) {
        const uint32_t* ag = Ab + kt * 16;
        const uint32_t* bg = Bb + (size_t)(kt * 16) * N;
        uint32_t ab = smb + 4 * (s * STAGE_U);
        uint32_t bb = ab + 4 * AS_U;
#pragma unroll
        for (int i = 0; i < 2; i++) {
            int id = tid + i * 256;
            int r = id >> 2, c = (id & 3) * 4;
            CP_ASYNC16(ab + (r * AS_STRIDE + c) * 4, ag + (size_t)r * GK2 + c);
        }
#pragma unroll
        for (int i = 0; i < 2; i++) {
            int id = tid + i * 256;
            int r = id >> 5, c = (id & 31) * 4;
            CP_ASYNC16(bb + (r * BS_STRIDE + c) * 4, bg + (size_t)r * N + c);
        }
        CP_COMMIT();
    };

    const int lmr = lane & 15;
    const int lmc = (lane >> 4) * 4;

    float acc[4][4][4];
#pragma unroll
    for (int i = 0; i < 4; i++)
#pragma unroll
        for (int j = 0; j < 4; j++)
#pragma unroll
            for (int k = 0; k < 4; k++) acc[i][j][k] = 0.f;

    load_tile(0, 0);
    load_tile(1, 1);

    for (int kt = 0; kt < NT; kt++) {
        if (kt < NT - 1) { CP_WAIT(1); } else { CP_WAIT(0); }
        __syncthreads();
        if (kt + 2 < NT) load_tile(kt + 2, (kt + 2) % NSTAGE);

        const uint32_t sbase = smb + 4 * ((kt % NSTAGE) * STAGE_U);
        const uint32_t* bs = sh + (kt % NSTAGE) * STAGE_U + AS_U;

#pragma unroll
        for (int ks = 0; ks < 2; ks++) {
            const int k0 = ks * 8;
            uint32_t afr[4][4];
#pragma unroll
            for (int mf = 0; mf < 4; mf++) {
                uint32_t ad = sbase +
                    4 * ((warp_m + mf * 16 + lmr) * AS_STRIDE + k0 + lmc);
                LDSM_X4(afr[mf][0], afr[mf][1], afr[mf][2], afr[mf][3], ad);
            }
            uint32_t bfr[4][2];
#pragma unroll
            for (int nf = 0; nf < 4; nf++) {
                const uint32_t* bp = bs + (k0 + tig) * BS_STRIDE + warp_n + nf * 8 + gid;
                bfr[nf][0] = bp[0];
                bfr[nf][1] = bp[4 * BS_STRIDE];
            }
#pragma unroll
            for (int mf = 0; mf < 4; mf++)
#pragma unroll
                for (int nf = 0; nf < 4; nf++)
                    mma_f16(acc[mf][nf], afr[mf], bfr[nf]);
        }
    }

#pragma unroll
    for (int mf = 0; mf < 4; mf++) {
#pragma unroll
        for (int nf = 0; nf < 4; nf++) {
            int row0 = by * 128 + warp_m + mf * 16 + gid;
            int col  = bx * 128 + warp_n + nf * 8 + tig * 2;
            if (pack) {
                uint32_t* Cp = (uint32_t*)C;
                Cp[(size_t)row0 * (N / 2) + col / 2] =
                    packh2(acc[mf][nf][0], acc[mf][nf][1]);
                Cp[(size_t)(row0 + 8) * (N / 2) + col / 2] =
                    packh2(acc[mf][nf][2], acc[mf][nf][3]);
            } else {
                float* Cf = (float*)C;
                float b0 = 0.f, b1 = 0.f;
                if (bias) { b0 = __ldg(bias + col); b1 = __ldg(bias + col + 1); }
                *(float2*)(Cf + (size_t)row0 * N + col) =
                    make_float2(acc[mf][nf][0] + b0, acc[mf][nf][1] + b1);
                *(float2*)(Cf + (size_t)(row0 + 8) * N + col) =
                    make_float2(acc[mf][nf][2] + b0, acc[mf][nf][3] + b1);
            }
        }
    }
}

// ---------------------------------------------------------------------------
// fp16 causal GQA flash attention — 128-row q tiles, double-buffered K/V,
// ONE barrier per key tile.  K and V are pure cp.async copies (raw packed
// layout); PV B-fragments via ldmatrix.x4.trans on raw V[key][d].
// ---------------------------------------------------------------------------
#define KSTR 68
#define PSTR 36
#define ATT_SMEM_UINTS (2 * 64 * KSTR + 2 * 64 * KSTR + 8 * 16 * PSTR) // 22016
#define ATT_SMEM_BYTES (ATT_SMEM_UINTS * 4)                            // 88064
#define QROW (D_DIM / 2)
#define KVROW (KVDIM / 2)

__global__ __launch_bounds__(256, 2) void attn_h(
    const uint32_t* __restrict__ qh2, const uint32_t* __restrict__ kvh2,
    uint32_t* __restrict__ ctxh)
{
    const int h  = blockIdx.x;
    const int qt = (T_LEN / 128 - 1) - blockIdx.y;   // heavy-first
    const int g  = h >> 2;

    extern __shared__ uint32_t smu[];
    uint32_t* Ksh[2] = { smu, smu + 64 * KSTR };
    uint32_t* Vsh[2] = { smu + 2 * 64 * KSTR, smu + 3 * 64 * KSTR };
    uint32_t* Psh = smu + 4 * 64 * KSTR;
    const uint32_t kb[2] = { smem_u32(Ksh[0]), smem_u32(Ksh[1]) };
    const uint32_t vb[2] = { smem_u32(Vsh[0]), smem_u32(Vsh[1]) };

    const int tid  = threadIdx.x;
    const int wid  = tid >> 5;
    const int lane = tid & 31;
    const int gid  = lane >> 2;
    const int tig  = lane & 3;

    uint32_t* Pw = Psh + wid * 16 * PSTR;
    const uint32_t pw_base = smem_u32(Pw);
    const int lmr = lane & 15;
    const int lmc = (lane >> 4) * 4;
    // V ldmatrix.trans addressing: lanes 0-15 rows, lanes 16-31 rows at +8 halfs
    const int vrow = lane & 15;
    const int vcolu = ((lane >> 4) & 1) * 4;

    const int r0 = qt * 128 + wid * 16;
    const int rowg0 = r0 + gid;
    const int rowg1 = r0 + gid + 8;

    // Loader: K tile 1024 chunks + V tile 1024 chunks; 8 per thread
    auto load_kv = [&](int kt, int s) {
        const uint32_t* kvb = kvh2 + (size_t)(kt * 64) * KVROW + g * 128;
#pragma unroll
        for (int i = 0; i < 4; i++) {
            int id = tid + i * 256;
            int row = id >> 4, c4 = (id & 15) * 4;
            CP_ASYNC16(kb[s] + 4 * (row * KSTR + c4),
                       kvb + (size_t)row * KVROW + c4);
            CP_ASYNC16(vb[s] + 4 * (row * KSTR + c4),
                       kvb + (size_t)row * KVROW + 64 + c4);
        }
        CP_COMMIT();
    };

    // Q fragments: direct u32 loads from packed q
    uint32_t qf[8][4];
    {
        const uint32_t* qb = qh2 + (size_t)rowg0 * QROW + h * (HDIM / 2);
#pragma unroll
        for (int kf = 0; kf < 8; kf++) {
            qf[kf][0] = qb[kf * 8 + tig];
            qf[kf][1] = qb[8 * QROW + kf * 8 + tig];
            qf[kf][2] = qb[kf * 8 + tig + 4];
            qf[kf][3] = qb[8 * QROW + kf * 8 + tig + 4];
        }
    }

    float o[16][4];
#pragma unroll
    for (int nf = 0; nf < 16; nf++)
#pragma unroll
        for (int j = 0; j < 4; j++) o[nf][j] = 0.f;
    float m0 = -1e30f, m1 = -1e30f, l0 = 0.f, l1 = 0.f;
    const float scale = 0.08838834764831845f;

    const int ktmax = 2 * qt + 1;
    load_kv(0, 0);

    for (int kt = 0; kt <= ktmax; kt++) {
        const int cur = kt & 1;
        CP_WAIT(0);
        __syncthreads();       // K/V(kt) visible; compute(kt-1) readers done
        if (kt < ktmax) load_kv(kt + 1, cur ^ 1);

        const uint32_t* Kc = Ksh[cur];

        // ---- S = Q @ K^T ----
        float sa[8][4];
#pragma unroll
        for (int nf = 0; nf < 8; nf++)
#pragma unroll
            for (int j = 0; j < 4; j++) sa[nf][j] = 0.f;

#pragma unroll
        for (int kf = 0; kf < 8; kf++) {
#pragma unroll
            for (int nf = 0; nf < 8; nf++) {
                const uint32_t* kp = Kc + (nf * 8 + gid) * KSTR + kf * 8 + tig;
                uint32_t bfr[2] = { kp[0], kp[4] };
                mma_f16(sa[nf], qf[kf], bfr);
            }
        }

        // ---- scale + causal mask ----
        const bool diag = (kt * 64 + 63 > rowg0);
#pragma unroll
        for (int nf = 0; nf < 8; nf++) {
            int c = kt * 64 + nf * 8 + 2 * tig;
#pragma unroll
            for (int j = 0; j < 4; j++) sa[nf][j] *= scale;
            if (diag) {
                if (c     > rowg0) sa[nf][0] = -1e30f;
                if (c + 1 > rowg0) sa[nf][1] = -1e30f;
                if (c     > rowg1) sa[nf][2] = -1e30f;
                if (c + 1 > rowg1) sa[nf][3] = -1e30f;
            }
        }

        float mx0 = -1e30f, mx1 = -1e30f;
#pragma unroll
        for (int nf = 0; nf < 8; nf++) {
            mx0 = fmaxf(mx0, fmaxf(sa[nf][0], sa[nf][1]));
            mx1 = fmaxf(mx1, fmaxf(sa[nf][2], sa[nf][3]));
        }
        mx0 = fmaxf(mx0, __shfl_xor_sync(0xffffffff, mx0, 1));
        mx0 = fmaxf(mx0, __shfl_xor_sync(0xffffffff, mx0, 2));
        mx1 = fmaxf(mx1, __shfl_xor_sync(0xffffffff, mx1, 1));
        mx1 = fmaxf(mx1, __shfl_xor_sync(0xffffffff, mx1, 2));

        float mn0 = fmaxf(m0, mx0), mn1 = fmaxf(m1, mx1);
        float al0 = __expf(m0 - mn0), al1 = __expf(m1 - mn1);

        float s0 = 0.f, s1 = 0.f;
#pragma unroll
        for (int nf = 0; nf < 8; nf++) {
            float p00 = __expf(sa[nf][0] - mn0);
            float p01 = __expf(sa[nf][1] - mn0);
            float p10 = __expf(sa[nf][2] - mn1);
            float p11 = __expf(sa[nf][3] - mn1);
            s0 += p00 + p01;
            s1 += p10 + p11;
            int kp = nf * 4 + tig;
            Pw[gid * PSTR + kp]       = packh2(p00, p01);
            Pw[(gid + 8) * PSTR + kp] = packh2(p10, p11);
        }
        s0 += __shfl_xor_sync(0xffffffff, s0, 1);
        s0 += __shfl_xor_sync(0xffffffff, s0, 2);
        s1 += __shfl_xor_sync(0xffffffff, s1, 1);
        s1 += __shfl_xor_sync(0xffffffff, s1, 2);

        l0 = l0 * al0 + s0;
        l1 = l1 * al1 + s1;
        m0 = mn0; m1 = mn1;

#pragma unroll
        for (int nf = 0; nf < 16; nf++) {
            o[nf][0] *= al0; o[nf][1] *= al0;
            o[nf][2] *= al1; o[nf][3] *= al1;
        }
        __syncwarp();

        // ---- O += P @ V (raw V + ldmatrix.trans B-fragments) ----
#pragma unroll
        for (int kf = 0; kf < 4; kf++) {
            uint32_t pa[4];
            uint32_t pad = pw_base + 4 * (lmr * PSTR + kf * 8 + lmc);
            LDSM_X4(pa[0], pa[1], pa[2], pa[3], pad);
#pragma unroll
            for (int nfp = 0; nfp < 8; nfp++) {
                uint32_t b0, b1, c0, c1;
                uint32_t vad = vb[cur] +
                    4 * ((kf * 16 + vrow) * KSTR + nfp * 8 + vcolu);
                LDSM_X4T(b0, b1, c0, c1, vad);
                uint32_t f0[2] = { b0, b1 };
                uint32_t f1[2] = { c0, c1 };
                mma_f16(o[2 * nfp],     pa, f0);
                mma_f16(o[2 * nfp + 1], pa, f1);
            }
        }
        __syncwarp();
    }

    float inv0 = 1.0f / l0, inv1 = 1.0f / l1;
    uint32_t* cb = ctxh + (size_t)rowg0 * QROW + h * (HDIM / 2);
#pragma unroll
    for (int nf = 0; nf < 16; nf++) {
        int cp = nf * 4 + tig;
        cb[cp] = packh2(o[nf][0] * inv0, o[nf][1] * inv0);
        cb[8 * QROW + cp] = packh2(o[nf][2] * inv1, o[nf][3] * inv1);
    }
}

// ---------------------------------------------------------------------------
// Launch
// ---------------------------------------------------------------------------
extern "C" void kernel_launch(void* const* d_in, const int* in_sizes, int n_in,
                              void* d_out, int out_size)
{
    const float* x   = (const float*)d_in[0];
    const float* Wq  = (const float*)d_in[1];
    const float* Wkv = (const float*)d_in[2];
    const float* Wo  = (const float*)d_in[3];
    const float* bo  = (const float*)d_in[4];
    float* out = (float*)d_out;

    uint32_t *qh2, *kvh2, *ctxh, *xh, *wqh, *wkvh, *woh;
    cudaGetSymbolAddress((void**)&qh2,  g_qh2);
    cudaGetSymbolAddress((void**)&kvh2, g_kvh2);
    cudaGetSymbolAddress((void**)&ctxh, g_ctxh);
    cudaGetSymbolAddress((void**)&xh,   g_xh);
    cudaGetSymbolAddress((void**)&wqh,  g_wqh);
    cudaGetSymbolAddress((void**)&wkvh, g_wkvh);
    cudaGetSymbolAddress((void**)&woh,  g_woh);

    cudaFuncSetAttribute(attn_h,
                         cudaFuncAttributeMaxDynamicSharedMemorySize,
                         ATT_SMEM_BYTES);
    cudaFuncSetAttribute(gemm_h,
                         cudaFuncAttributeMaxDynamicSharedMemorySize,
                         GSMEM_BYTES);

    // Prepass: pack everything (vectorized, one launch)
    pack_all<<<(STOT / 4 + 255) / 256, 256>>>(x, Wq, Wkv, Wo, xh, wqh, wkvh, woh);

    // 1+2) fused: q = x@Wq (bx<32, packed), kv = x@Wkv (bx>=32, packed)
    gemm_h<<<dim3(D_DIM / 128 + KVDIM / 128, T_LEN / 128), 256, GSMEM_BYTES>>>(
        xh, wqh, qh2, nullptr, D_DIM, D_DIM / 128, 1, wkvh, kvh2, KVDIM, 1);
    // 3) attention (fp16, double-buffered K/V, 1 barrier/tile)
    attn_h<<<dim3(NHEAD, T_LEN / 128), 256, ATT_SMEM_BYTES>>>(qh2, kvh2, ctxh);
    // 4) out = ctx @ Wo + bo (f32 output)
    gemm_h<<<dim3(D_DIM / 128, T_LEN / 128), 256, GSMEM_BYTES>>>(
        ctxh, woh, out, bo, D_DIM, D_DIM / 128, 0, woh, out, D_DIM, 0);

    (void)in_sizes; (void)n_in; (void)out_size;
}